// round 8
// baseline (speedup 1.0000x reference)
#include <cuda_runtime.h>
#include <cuda.h>
#include <cuda_bf16.h>
#include <cstdint>
#include <cstddef>

using bf16 = __nv_bfloat16;

#define NTOK 4096
#define DIN  2048
#define DKQ  2048
#define DV   2048

// Arch-specific feature gate: tcgen05/TMEM exist only on the compute_103a
// target pass. On base sm_103 passes we compile an FFMA fallback.
#if defined(__CUDA_ARCH_FEAT_SM103_ALL) || defined(__CUDA_ARCH_FEAT_SM100_ALL)
#define HAS_TCGEN05 1
#else
#define HAS_TCGEN05 0
#endif

__device__ __forceinline__ uint32_t smem_u32(const void* p) {
    uint32_t a;
    asm("{ .reg .u64 t; cvta.to.shared.u64 t, %1; cvt.u32.u64 %0, t; }" : "=r"(a) : "l"(p));
    return a;
}

#if HAS_TCGEN05
__device__ __forceinline__ uint32_t elect_one_pred() {
    uint32_t pred;
    asm volatile("{\n\t.reg .pred p;\n\telect.sync _|p, 0xFFFFFFFF;\n\tselp.b32 %0, 1, 0, p;\n\t}" : "=r"(pred));
    return pred;
}
__device__ __forceinline__ uint32_t cluster_rank() {
    uint32_t r;
    asm("mov.u32 %0, %%cluster_ctarank;" : "=r"(r));
    return r;
}
#define TCGEN05_ALLOC(sa, n) \
    asm volatile("tcgen05.alloc.cta_group::1.sync.aligned.shared::cta.b32 [%0], %1;" \
        :: "r"((uint32_t)(sa)), "r"((uint32_t)(n)) : "memory")
#define TCGEN05_DEALLOC(t, n) \
    asm volatile("tcgen05.dealloc.cta_group::1.sync.aligned.b32 %0, %1;" :: "r"(t), "r"((uint32_t)(n)))
#define TCGEN05_RELINQ() \
    asm volatile("tcgen05.relinquish_alloc_permit.cta_group::1.sync.aligned;")
#define TCGEN05_COMMIT(mb) \
    asm volatile("tcgen05.commit.cta_group::1.mbarrier::arrive::one.shared::cluster.b64 [%0];" \
        :: "r"((uint32_t)(mb)) : "memory")
#define TCGEN05_COMMIT_MCAST(mb, mask) \
    asm volatile("tcgen05.commit.cta_group::1.mbarrier::arrive::one.shared::cluster.multicast::cluster.b64 [%0], %1;" \
        :: "r"((uint32_t)(mb)), "h"((uint16_t)(mask)) : "memory")
#define TCGEN05_WAIT_LD() asm volatile("tcgen05.wait::ld.sync.aligned;" ::: "memory")
#define TCGEN05_FENCE_AFTER() asm volatile("tcgen05.fence::after_thread_sync;" ::: "memory")
#define TCGEN05_FENCE_BEFORE() asm volatile("tcgen05.fence::before_thread_sync;" ::: "memory")
#define MBARRIER_INIT(mb, c) \
    asm volatile("mbarrier.init.shared.b64 [%0], %1;" :: "r"((uint32_t)(mb)), "r"((uint32_t)(c)) : "memory")
#define MBARRIER_INVAL(mb) \
    asm volatile("mbarrier.inval.shared.b64 [%0];" :: "r"((uint32_t)(mb)) : "memory")
#define MBARRIER_EXPECT_TX(mb, b) \
    asm volatile("mbarrier.arrive.expect_tx.shared.b64 _, [%0], %1;" \
        :: "r"((uint32_t)(mb)), "r"((uint32_t)(b)) : "memory")
#define MBARRIER_WAIT_PARITY(mb, par) do { \
    uint32_t _mb = (uint32_t)(mb); uint32_t _p = (uint32_t)(par); uint32_t _d; \
    asm volatile("{\n\t.reg .pred p;\n\t" \
        "mbarrier.try_wait.parity.acquire.cta.shared::cta.b64 p, [%1], %2;\n\t" \
        "selp.b32 %0, 1, 0, p;\n\t}" : "=r"(_d) : "r"(_mb), "r"(_p) : "memory"); \
    if (!_d) { \
        asm volatile("{\n\t.reg .pred P1;\n\t" \
            "WAIT_LOOP_%=:\n\t" \
            "mbarrier.try_wait.parity.acquire.cta.shared::cta.b64 P1, [%0], %1, 0x989680;\n\t" \
            "@P1 bra.uni WAIT_DONE_%=;\n\t" \
            "bra.uni WAIT_LOOP_%=;\n\t" \
            "WAIT_DONE_%=:\n\t}" :: "r"(_mb), "r"(_p) : "memory"); \
    } } while (0)
#define CLUSTER_ARRIVE() asm volatile("barrier.cluster.arrive.aligned;" ::: "memory")
#define CLUSTER_WAIT()   asm volatile("barrier.cluster.wait.aligned;" ::: "memory")
#define TCGEN05_LD_32X32B_X32(r, ta) \
    asm volatile("tcgen05.ld.sync.aligned.32x32b.x32.b32 " \
        "{%0, %1, %2, %3, %4, %5, %6, %7, %8, %9, %10, %11, %12, %13, %14, %15, " \
        " %16, %17, %18, %19, %20, %21, %22, %23, %24, %25, %26, %27, %28, %29, %30, %31}, [%32];" \
        : "=r"((r)[0]),  "=r"((r)[1]),  "=r"((r)[2]),  "=r"((r)[3]), \
          "=r"((r)[4]),  "=r"((r)[5]),  "=r"((r)[6]),  "=r"((r)[7]), \
          "=r"((r)[8]),  "=r"((r)[9]),  "=r"((r)[10]), "=r"((r)[11]), \
          "=r"((r)[12]), "=r"((r)[13]), "=r"((r)[14]), "=r"((r)[15]), \
          "=r"((r)[16]), "=r"((r)[17]), "=r"((r)[18]), "=r"((r)[19]), \
          "=r"((r)[20]), "=r"((r)[21]), "=r"((r)[22]), "=r"((r)[23]), \
          "=r"((r)[24]), "=r"((r)[25]), "=r"((r)[26]), "=r"((r)[27]), \
          "=r"((r)[28]), "=r"((r)[29]), "=r"((r)[30]), "=r"((r)[31]) \
        : "r"(ta))

__device__ __forceinline__ void tma_load_2d(uint32_t smem_addr, const void* map,
                                            int cx, int cy, uint32_t mbar) {
    asm volatile(
        "cp.async.bulk.tensor.2d.shared::cta.global.tile.mbarrier::complete_tx::bytes "
        "[%0], [%1, {%2, %3}], [%4];"
        :: "r"(smem_addr), "l"(map), "r"(cx), "r"(cy), "r"(mbar) : "memory");
}
__device__ __forceinline__ void tma_load_2d_mcast(uint32_t smem_addr, const void* map,
                                                  int cx, int cy, uint32_t mbar,
                                                  uint16_t mask) {
    asm volatile(
        "cp.async.bulk.tensor.2d.shared::cluster.global.tile.mbarrier::complete_tx::bytes.multicast::cluster "
        "[%0], [%1, {%2, %3}], [%4], %5;"
        :: "r"(smem_addr), "l"(map), "r"(cx), "r"(cy), "r"(mbar), "h"(mask) : "memory");
}

// K-major SW128 smem descriptor (LBO=1, SBO=64, version=1, layout=SW128)
static constexpr uint64_t SMEM_DESC_BASE_SW128 =
    (uint64_t(2) << 61) | (uint64_t(1) << 46) | (uint64_t(64) << 32) | (uint64_t(1) << 16);
#define MAKE_SMEM_DESC(a) (SMEM_DESC_BASE_SW128 | ((uint64_t)((a) >> 4) & 0x3FFF))

// kind::f16 SS mma, bf16 in, fp32 acc, M=128, N=256, K-major both
static constexpr uint32_t MMA_IDESC_N256 =
    (1u << 4) | (1u << 7) | (1u << 10) | ((256u / 8u) << 17) | ((128u / 16u) << 24);

__device__ __forceinline__ void mma_f16_ss(uint32_t d, uint64_t a, uint64_t b, bool en) {
    uint32_t e = en ? 1u : 0u;
    asm volatile(
        "{\n\t.reg .pred p;\n\t"
        "setp.ne.u32 p, %5, 0;\n\t"
        "tcgen05.mma.cta_group::1.kind::f16 [%0], %1, %2, %3, {%4, %4, %4, %4}, p;\n\t"
        "}"
        :: "r"(d), "l"(a), "l"(b), "r"(MMA_IDESC_N256), "r"(0u), "r"(e)
        : "memory");
}
#endif  // HAS_TCGEN05

#define SW128(x) ((x) ^ (((x) >> 3) & 0x70))

// ---------------------------------------------------------------------------
// Scratch (device globals; allocation-free rule)
// ---------------------------------------------------------------------------
__device__ bf16  g_x0[(size_t)NTOK * DIN],  g_x1[(size_t)NTOK * DIN];
__device__ bf16  g_Wt0[(size_t)DKQ * DIN],  g_Wt1[(size_t)DKQ * DIN];
__device__ bf16  g_Q0[(size_t)NTOK * DKQ],  g_Q1[(size_t)NTOK * DKQ];
__device__ bf16  g_K0[(size_t)NTOK * DKQ],  g_K1[(size_t)NTOK * DKQ];
__device__ bf16  g_Vt0[(size_t)DV * NTOK],  g_Vt1[(size_t)DV * NTOK];
__device__ float g_S [(size_t)NTOK * NTOK];
__device__ bf16  g_P0[(size_t)NTOK * NTOK], g_P1[(size_t)NTOK * NTOK];

// ---------------------------------------------------------------------------
// tcgen05 TMA-fed GEMM: C[M,N] ~= (A0+A1) @ (B0+B1)^T  via A0B0+A0B1+A1B0.
// M_TILE=128, N_TILE=256, K_chunk=64, 2-stage pipeline, warp-specialized.
// Cluster (1,2,1): the two CTAs share bn; B tiles are TMA-multicast (1 L2 read
// serves both), A tiles per-CTA. Empty barriers count=2, released by multicast
// tcgen05.commit from BOTH consumers (peer copy must be consumed before rank 0
// re-issues B into the stage).
// EPI 1: (+channel bias)*rsqrt(dkq) fp32.  EPI 2: +e0+e1+(c&1) fp32.
// EPI 3: bf16x2 split store (row-major).   EPI 4: bf16x2 split store TRANSPOSED.
// ---------------------------------------------------------------------------
#define OFF_A0 0
#define OFF_A1 (16 * 1024)
#define OFF_B0 (32 * 1024)
#define OFF_B1 (64 * 1024)
#define STAGE_BYTES (96 * 1024)
#define GEMM_SMEM  (1024 + 2 * STAGE_BYTES)   // 197632

template<int EPI>
__global__ __launch_bounds__(256, 1) __cluster_dims__(1, 2, 1)
void mma_gemm(const __grid_constant__ CUtensorMap ma0,
              const __grid_constant__ CUtensorMap ma1,
              const __grid_constant__ CUtensorMap mb0,
              const __grid_constant__ CUtensorMap mb1,
              const bf16* __restrict__ A0, const bf16* __restrict__ A1,
              const bf16* __restrict__ B0, const bf16* __restrict__ B1,
              int N, int K,
              float* __restrict__ Cf, bf16* __restrict__ C0, bf16* __restrict__ C1,
              const float* __restrict__ e0, const float* __restrict__ e1)
{
#if HAS_TCGEN05
    extern __shared__ char smem[];
    const uint32_t sb = smem_u32(smem);
    const int tid = threadIdx.x;
    const int wid = tid >> 5;
    const int lid = tid & 31;
    const int bm = blockIdx.y * 128;
    const int bn = blockIdx.x * 256;
    const uint32_t rank = cluster_rank();

    // barriers: full0=16, full1=24, empty0=32, empty1=40, done=48
    if (wid == 0) {
        TCGEN05_ALLOC(sb + 0, 256);
        TCGEN05_RELINQ();
    }
    if (tid == 0) {
        MBARRIER_INIT(sb + 16, 1);
        MBARRIER_INIT(sb + 24, 1);
        MBARRIER_INIT(sb + 32, 2);   // empty: multicast commits from BOTH consumers
        MBARRIER_INIT(sb + 40, 2);
        MBARRIER_INIT(sb + 48, 1);
    }
    __syncthreads();
    // peer barriers must be initialized before any multicast targets them
    CLUSTER_ARRIVE();
    CLUSTER_WAIT();

    uint32_t tmem;
    asm volatile("ld.shared.b32 %0, [%1];" : "=r"(tmem) : "r"(sb + 0));

    const int NC = K >> 6;

    if (wid == 7) {
        // ---------------- TMA producer ----------------
        if (elect_one_pred()) {
            int pe0 = 0, pe1 = 0;
            for (int ch = 0; ch < NC; ch++) {
                const int s = ch & 1;
                const uint32_t stg = sb + 1024 + s * STAGE_BYTES;
                if (ch >= 2) {
                    if (s == 0) { MBARRIER_WAIT_PARITY(sb + 32, pe0); pe0 ^= 1; }
                    else        { MBARRIER_WAIT_PARITY(sb + 40, pe1); pe1 ^= 1; }
                }
                const uint32_t fullb = sb + 16 + s * 8;
                MBARRIER_EXPECT_TX(fullb, STAGE_BYTES);
                const int kx = ch * 64;
                tma_load_2d(stg + OFF_A0, &ma0, kx, bm, fullb);
                tma_load_2d(stg + OFF_A1, &ma1, kx, bm, fullb);
                if (rank == 0) {
                    // one L2 read delivers B to both CTAs' stage + both full barriers
                    tma_load_2d_mcast(stg + OFF_B0, &mb0, kx, bn, fullb, 3);
                    tma_load_2d_mcast(stg + OFF_B1, &mb1, kx, bn, fullb, 3);
                }
            }
        }
    } else if (wid == 6) {
        // ---------------- MMA consumer ----------------
        if (elect_one_pred()) {
            int pf0 = 0, pf1 = 0;
            for (int ch = 0; ch < NC; ch++) {
                const int s = ch & 1;
                const uint32_t stg = sb + 1024 + s * STAGE_BYTES;
                if (s == 0) { MBARRIER_WAIT_PARITY(sb + 16, pf0); pf0 ^= 1; }
                else        { MBARRIER_WAIT_PARITY(sb + 24, pf1); pf1 ^= 1; }
                const uint64_t dA0 = MAKE_SMEM_DESC(stg + OFF_A0);
                const uint64_t dA1 = MAKE_SMEM_DESC(stg + OFF_A1);
                const uint64_t dB0 = MAKE_SMEM_DESC(stg + OFF_B0);
                const uint64_t dB1 = MAKE_SMEM_DESC(stg + OFF_B1);
#pragma unroll
                for (int ks = 0; ks < 4; ks++) {
                    const uint64_t o = (uint64_t)(ks * 2);   // +32B per 16-elem K step
                    mma_f16_ss(tmem, dA0 + o, dB0 + o, (ch > 0) || (ks > 0));
                    mma_f16_ss(tmem, dA0 + o, dB1 + o, true);
                    mma_f16_ss(tmem, dA1 + o, dB0 + o, true);
                }
                // release stage in BOTH CTAs (peer must not refill our B copy early)
                TCGEN05_COMMIT_MCAST(sb + 32 + s * 8, 3);
            }
            TCGEN05_COMMIT(sb + 48);               // done (local)
        }
    }

    // everyone waits for all MMAs
    MBARRIER_WAIT_PARITY(sb + 48, 0);
    TCGEN05_FENCE_AFTER();

    // ---------------- epilogue: warps 0-3, 32 rows x 256 cols each ----------
    if (tid < 128) {
        const int r0 = bm + wid * 32;
        float* tp = ((float*)(smem + 1024)) + wid * (33 * 32);
#pragma unroll 1
        for (int cb = 0; cb < 8; cb++) {
            uint32_t d[32];
            TCGEN05_LD_32X32B_X32(d, tmem + cb * 32);
            TCGEN05_WAIT_LD();
            const int cbase = bn + cb * 32;
            if (EPI == 4) {
                // transposed split store: lane=row -> contiguous, coalesced
                const int r = r0 + lid;
#pragma unroll
                for (int j = 0; j < 32; j++) {
                    float v = __uint_as_float(d[j]);
                    bf16 h = __float2bfloat16(v);
                    const size_t idx = (size_t)(cbase + j) * NTOK + r;
                    C0[idx] = h;
                    C1[idx] = __float2bfloat16(v - __bfloat162float(h));
                }
            } else {
                // smem transpose so stores are coalesced (lane = col)
#pragma unroll
                for (int j = 0; j < 32; j++) tp[lid * 33 + j] = __uint_as_float(d[j]);
                __syncwarp();
                const int c = cbase + lid;
#pragma unroll 1
                for (int i = 0; i < 32; i++) {
                    const int r = r0 + i;
                    const float v = tp[i * 33 + lid];
                    const size_t idx = (size_t)r * N + c;
                    if (EPI == 1) {
                        Cf[idx] = (v + (((r >> 6) == (c >> 6)) ? 1.0f : 0.0f))
                                  * 0.022097086912079608f;   // 1/sqrt(2048)
                    } else if (EPI == 2) {
                        Cf[idx] = v + e0[idx] + e1[idx] + (float)(c & 1);
                    } else {  // EPI == 3
                        bf16 h = __float2bfloat16(v);
                        C0[idx] = h;
                        C1[idx] = __float2bfloat16(v - __bfloat162float(h));
                    }
                }
                __syncwarp();
            }
        }
        TCGEN05_FENCE_BEFORE();
    }
    __syncthreads();
    if (tid == 0) {
        MBARRIER_INVAL(sb + 16); MBARRIER_INVAL(sb + 24);
        MBARRIER_INVAL(sb + 32); MBARRIER_INVAL(sb + 40);
        MBARRIER_INVAL(sb + 48);
    }
    __syncthreads();
    if (wid == 0) TCGEN05_DEALLOC(tmem, 256);
    // no CTA may exit while peer multicast could target its smem/barriers
    CLUSTER_ARRIVE();
    CLUSTER_WAIT();
#else
    // ================= FFMA fallback (base sm_103): two 128-col halves ======
    extern __shared__ char smemraw[];
    float* Asf = (float*)smemraw;            // [2][8][128]
    float* Bsf = Asf + 2 * 8 * 128;          // [2][8][128]

    const int t  = threadIdx.x;
    const int bm = blockIdx.y * 128;
    const int arow = t >> 1;
    const int acol = (t & 1) << 2;
    const int tx = t & 15;
    const int ty = t >> 4;

    for (int half = 0; half < 2; half++) {
        const int bn = blockIdx.x * 256 + half * 128;
        const bf16* A0p = A0 + (size_t)(bm + arow) * K + acol;
        const bf16* A1p = A1 + (size_t)(bm + arow) * K + acol;
        const bf16* B0p = B0 + (size_t)(bn + arow) * K + acol;
        const bf16* B1p = B1 + (size_t)(bn + arow) * K + acol;

        float acc[8][8];
#pragma unroll
        for (int i = 0; i < 8; i++)
#pragma unroll
            for (int j = 0; j < 8; j++) acc[i][j] = 0.0f;

        {
            const __nv_bfloat162* qa0 = (const __nv_bfloat162*)A0p;
            const __nv_bfloat162* qa1 = (const __nv_bfloat162*)A1p;
            const __nv_bfloat162* qb0 = (const __nv_bfloat162*)B0p;
            const __nv_bfloat162* qb1 = (const __nv_bfloat162*)B1p;
            float2 a0 = __bfloat1622float2(qa0[0]), a1 = __bfloat1622float2(qa0[1]);
            float2 c0 = __bfloat1622float2(qa1[0]), c1 = __bfloat1622float2(qa1[1]);
            float2 b0 = __bfloat1622float2(qb0[0]), b1 = __bfloat1622float2(qb0[1]);
            float2 d0 = __bfloat1622float2(qb1[0]), d1 = __bfloat1622float2(qb1[1]);
            Asf[(acol + 0) * 128 + arow] = a0.x + c0.x;
            Asf[(acol + 1) * 128 + arow] = a0.y + c0.y;
            Asf[(acol + 2) * 128 + arow] = a1.x + c1.x;
            Asf[(acol + 3) * 128 + arow] = a1.y + c1.y;
            Bsf[(acol + 0) * 128 + arow] = b0.x + d0.x;
            Bsf[(acol + 1) * 128 + arow] = b0.y + d0.y;
            Bsf[(acol + 2) * 128 + arow] = b1.x + d1.x;
            Bsf[(acol + 3) * 128 + arow] = b1.y + d1.y;
        }
        __syncthreads();

        const int KT = K >> 3;
        int buf = 0;
        for (int kt = 0; kt < KT; kt++) {
            float4 aN = make_float4(0, 0, 0, 0), bN = make_float4(0, 0, 0, 0);
            const bool has = (kt + 1 < KT);
            if (has) {
                const size_t o = (size_t)(kt + 1) * 8;
                const __nv_bfloat162* qa0 = (const __nv_bfloat162*)(A0p + o);
                const __nv_bfloat162* qa1 = (const __nv_bfloat162*)(A1p + o);
                const __nv_bfloat162* qb0 = (const __nv_bfloat162*)(B0p + o);
                const __nv_bfloat162* qb1 = (const __nv_bfloat162*)(B1p + o);
                float2 a0 = __bfloat1622float2(qa0[0]), a1 = __bfloat1622float2(qa0[1]);
                float2 c0 = __bfloat1622float2(qa1[0]), c1 = __bfloat1622float2(qa1[1]);
                float2 b0 = __bfloat1622float2(qb0[0]), b1 = __bfloat1622float2(qb0[1]);
                float2 d0 = __bfloat1622float2(qb1[0]), d1 = __bfloat1622float2(qb1[1]);
                aN = make_float4(a0.x + c0.x, a0.y + c0.y, a1.x + c1.x, a1.y + c1.y);
                bN = make_float4(b0.x + d0.x, b0.y + d0.y, b1.x + d1.x, b1.y + d1.y);
            }
            const float* Ab = Asf + buf * 1024;
            const float* Bb = Bsf + buf * 1024;
#pragma unroll
            for (int k = 0; k < 8; k++) {
                float4 a0 = *(const float4*)&Ab[k * 128 + ty * 4];
                float4 a1 = *(const float4*)&Ab[k * 128 + 64 + ty * 4];
                float4 b0 = *(const float4*)&Bb[k * 128 + tx * 4];
                float4 b1 = *(const float4*)&Bb[k * 128 + 64 + tx * 4];
                float av[8] = {a0.x, a0.y, a0.z, a0.w, a1.x, a1.y, a1.z, a1.w};
                float bv[8] = {b0.x, b0.y, b0.z, b0.w, b1.x, b1.y, b1.z, b1.w};
#pragma unroll
                for (int i = 0; i < 8; i++)
#pragma unroll
                    for (int j = 0; j < 8; j++)
                        acc[i][j] = fmaf(av[i], bv[j], acc[i][j]);
            }
            if (has) {
                const int nb = buf ^ 1;
                float* An = Asf + nb * 1024;
                float* Bn = Bsf + nb * 1024;
                An[(acol + 0) * 128 + arow] = aN.x; An[(acol + 1) * 128 + arow] = aN.y;
                An[(acol + 2) * 128 + arow] = aN.z; An[(acol + 3) * 128 + arow] = aN.w;
                Bn[(acol + 0) * 128 + arow] = bN.x; Bn[(acol + 1) * 128 + arow] = bN.y;
                Bn[(acol + 2) * 128 + arow] = bN.z; Bn[(acol + 3) * 128 + arow] = bN.w;
            }
            __syncthreads();
            buf ^= 1;
        }

#pragma unroll
        for (int i = 0; i < 8; i++) {
            const int r = bm + ((i < 4) ? (ty * 4 + i) : (64 + ty * 4 + (i - 4)));
#pragma unroll
            for (int j = 0; j < 8; j++) {
                const int c = bn + ((j < 4) ? (tx * 4 + j) : (64 + tx * 4 + (j - 4)));
                float v = acc[i][j];
                if (EPI == 1) {
                    Cf[(size_t)r * N + c] =
                        (v + (((r >> 6) == (c >> 6)) ? 1.0f : 0.0f)) * 0.022097086912079608f;
                } else if (EPI == 2) {
                    const size_t idx = (size_t)r * N + c;
                    Cf[idx] = v + e0[idx] + e1[idx] + (float)(c & 1);
                } else if (EPI == 3) {
                    const size_t idx = (size_t)r * N + c;
                    bf16 h = __float2bfloat16(v);
                    C0[idx] = h;
                    C1[idx] = __float2bfloat16(v - __bfloat162float(h));
                } else {  // EPI == 4: transposed split
                    const size_t idx = (size_t)c * NTOK + r;
                    bf16 h = __float2bfloat16(v);
                    C0[idx] = h;
                    C1[idx] = __float2bfloat16(v - __bfloat162float(h));
                }
            }
        }
        __syncthreads();
    }
#endif
}

// ---------------------------------------------------------------------------
// bf16x2 split and transpose-split
// ---------------------------------------------------------------------------
__global__ __launch_bounds__(256)
void split_kernel(const float* __restrict__ in, bf16* __restrict__ o0,
                  bf16* __restrict__ o1, int n)
{
    int i = blockIdx.x * 256 + threadIdx.x;
    if (i < n) {
        float v = in[i];
        bf16 h = __float2bfloat16(v);
        o0[i] = h;
        o1[i] = __float2bfloat16(v - __bfloat162float(h));
    }
}

__global__ __launch_bounds__(256)
void transpose_split_kernel(const float* __restrict__ in, bf16* __restrict__ o0,
                            bf16* __restrict__ o1, int R, int C)
{
    __shared__ float tile[32][33];
    const int c0 = blockIdx.x * 32;
    const int r0 = blockIdx.y * 32;
    const int tx = threadIdx.x & 31;
    const int ty = threadIdx.x >> 5;
#pragma unroll
    for (int i = 0; i < 32; i += 8)
        tile[ty + i][tx] = in[(size_t)(r0 + ty + i) * C + c0 + tx];
    __syncthreads();
#pragma unroll
    for (int i = 0; i < 32; i += 8) {
        float v = tile[tx][ty + i];
        const size_t idx = (size_t)(c0 + ty + i) * R + r0 + tx;
        bf16 h = __float2bfloat16(v);
        o0[idx] = h;
        o1[idx] = __float2bfloat16(v - __bfloat162float(h));
    }
}

// ---------------------------------------------------------------------------
// Row softmax over S[4096,4096] -> bf16x2 split P
// ---------------------------------------------------------------------------
__device__ __forceinline__ float warpMax(float v) {
#pragma unroll
    for (int o = 16; o > 0; o >>= 1) v = fmaxf(v, __shfl_xor_sync(0xffffffffu, v, o));
    return v;
}
__device__ __forceinline__ float warpSum(float v) {
#pragma unroll
    for (int o = 16; o > 0; o >>= 1) v += __shfl_xor_sync(0xffffffffu, v, o);
    return v;
}

__global__ __launch_bounds__(256)
void softmax_split_kernel(const float* __restrict__ S, bf16* __restrict__ P0,
                          bf16* __restrict__ P1)
{
    __shared__ float red[8];
    __shared__ float bcast;
    const int rowi = blockIdx.x;
    const int t = threadIdx.x;
    const float* __restrict__ Sr = S + (size_t)rowi * NTOK;

    float v[16];
    float m = -3.402823466e38f;
#pragma unroll
    for (int i = 0; i < 16; i++) {
        v[i] = Sr[t + i * 256];
        m = fmaxf(m, v[i]);
    }
    m = warpMax(m);
    if ((t & 31) == 0) red[t >> 5] = m;
    __syncthreads();
    if (t < 32) {
        float x = (t < 8) ? red[t] : -3.402823466e38f;
        x = warpMax(x);
        if (t == 0) bcast = x;
    }
    __syncthreads();
    m = bcast;

    float s = 0.0f;
#pragma unroll
    for (int i = 0; i < 16; i++) {
        v[i] = expf(v[i] - m);
        s += v[i];
    }
    s = warpSum(s);
    if ((t & 31) == 0) red[t >> 5] = s;
    __syncthreads();
    if (t < 32) {
        float x = (t < 8) ? red[t] : 0.0f;
        x = warpSum(x);
        if (t == 0) bcast = x;
    }
    __syncthreads();
    const float inv = 1.0f / bcast;
#pragma unroll
    for (int i = 0; i < 16; i++) {
        const float p = v[i] * inv;
        const size_t idx = (size_t)rowi * NTOK + t + i * 256;
        bf16 h = __float2bfloat16(p);
        P0[idx] = h;
        P1[idx] = __float2bfloat16(p - __bfloat162float(h));
    }
}

// ---------------------------------------------------------------------------
// Host: tensormap encoding via runtime-resolved driver entry point (no -lcuda)
// ---------------------------------------------------------------------------
typedef CUresult (*TMEncodeFn)(
    CUtensorMap*, CUtensorMapDataType, cuuint32_t, void*,
    const cuuint64_t*, const cuuint64_t*, const cuuint32_t*, const cuuint32_t*,
    CUtensorMapInterleave, CUtensorMapSwizzle, CUtensorMapL2promotion,
    CUtensorMapFloatOOBfill);

static TMEncodeFn get_encoder() {
    void* fn = nullptr;
    cudaDriverEntryPointQueryResult st;
    cudaGetDriverEntryPointByVersion("cuTensorMapEncodeTiled", &fn, 12000,
                                     cudaEnableDefault, &st);
    return (TMEncodeFn)fn;
}

// bf16 K-major 2D map: dims {K, R}, box {64, boxR}, SW128
static void encode_map(TMEncodeFn enc, CUtensorMap* m, const void* ptr,
                       uint64_t Kdim, uint64_t R, uint32_t boxR) {
    cuuint64_t dims[2]    = {(cuuint64_t)Kdim, (cuuint64_t)R};
    cuuint64_t strides[1] = {(cuuint64_t)(Kdim * 2)};
    cuuint32_t box[2]     = {64u, boxR};
    cuuint32_t es[2]      = {1u, 1u};
    enc(m, CU_TENSOR_MAP_DATA_TYPE_BFLOAT16, 2, (void*)ptr, dims, strides, box, es,
        CU_TENSOR_MAP_INTERLEAVE_NONE, CU_TENSOR_MAP_SWIZZLE_128B,
        CU_TENSOR_MAP_L2_PROMOTION_L2_128B, CU_TENSOR_MAP_FLOAT_OOB_FILL_NONE);
}

extern "C" void kernel_launch(void* const* d_in, const int* in_sizes, int n_in,
                              void* d_out, int out_size)
{
    const float* x   = (const float*)d_in[0];
    const float* Wq  = (const float*)d_in[1];
    const float* Wk  = (const float*)d_in[2];
    const float* Wv  = (const float*)d_in[3];
    const float* bch = (const float*)d_in[4];
    const float* bt  = (const float*)d_in[5];   // step 0 slice
    float* out = (float*)d_out;

    bf16 *x0, *x1, *Wt0, *Wt1, *Q0, *Q1, *K0, *K1, *Vt0, *Vt1, *P0, *P1;
    float *S;
    cudaGetSymbolAddress((void**)&x0, g_x0);   cudaGetSymbolAddress((void**)&x1, g_x1);
    cudaGetSymbolAddress((void**)&Wt0, g_Wt0); cudaGetSymbolAddress((void**)&Wt1, g_Wt1);
    cudaGetSymbolAddress((void**)&Q0, g_Q0);   cudaGetSymbolAddress((void**)&Q1, g_Q1);
    cudaGetSymbolAddress((void**)&K0, g_K0);   cudaGetSymbolAddress((void**)&K1, g_K1);
    cudaGetSymbolAddress((void**)&Vt0, g_Vt0); cudaGetSymbolAddress((void**)&Vt1, g_Vt1);
    cudaGetSymbolAddress((void**)&S, g_S);
    cudaGetSymbolAddress((void**)&P0, g_P0);   cudaGetSymbolAddress((void**)&P1, g_P1);

    TMEncodeFn enc = get_encoder();

    CUtensorMap mx0, mx1, mW0, mW1, mQ0, mQ1, mK0, mK1, mV0, mV1, mP0, mP1;
    encode_map(enc, &mx0, x0,  DIN,  NTOK, 128);  // A role
    encode_map(enc, &mx1, x1,  DIN,  NTOK, 128);
    encode_map(enc, &mW0, Wt0, DIN,  DKQ,  256);  // B role
    encode_map(enc, &mW1, Wt1, DIN,  DKQ,  256);
    encode_map(enc, &mQ0, Q0,  DKQ,  NTOK, 128);
    encode_map(enc, &mQ1, Q1,  DKQ,  NTOK, 128);
    encode_map(enc, &mK0, K0,  DKQ,  NTOK, 256);
    encode_map(enc, &mK1, K1,  DKQ,  NTOK, 256);
    encode_map(enc, &mV0, Vt0, NTOK, DV,   256);
    encode_map(enc, &mV1, Vt1, NTOK, DV,   256);
    encode_map(enc, &mP0, P0,  NTOK, NTOK, 128);
    encode_map(enc, &mP1, P1,  NTOK, NTOK, 128);

    cudaFuncSetAttribute(mma_gemm<1>, cudaFuncAttributeMaxDynamicSharedMemorySize, GEMM_SMEM);
    cudaFuncSetAttribute(mma_gemm<2>, cudaFuncAttributeMaxDynamicSharedMemorySize, GEMM_SMEM);
    cudaFuncSetAttribute(mma_gemm<3>, cudaFuncAttributeMaxDynamicSharedMemorySize, GEMM_SMEM);
    cudaFuncSetAttribute(mma_gemm<4>, cudaFuncAttributeMaxDynamicSharedMemorySize, GEMM_SMEM);

    // split x
    split_kernel<<<(NTOK * DIN) / 256, 256>>>(x, x0, x1, NTOK * DIN);

    const dim3 gProj(DKQ / 256, NTOK / 128);   // (8, 32)
    // Q = x @ Wq
    transpose_split_kernel<<<dim3(DKQ / 32, DIN / 32), 256>>>(Wq, Wt0, Wt1, DIN, DKQ);
    mma_gemm<3><<<gProj, 256, GEMM_SMEM>>>(mx0, mx1, mW0, mW1,
                                           x0, x1, Wt0, Wt1, DKQ, DIN,
                                           nullptr, Q0, Q1, nullptr, nullptr);
    // K = x @ Wk
    transpose_split_kernel<<<dim3(DKQ / 32, DIN / 32), 256>>>(Wk, Wt0, Wt1, DIN, DKQ);
    mma_gemm<3><<<gProj, 256, GEMM_SMEM>>>(mx0, mx1, mW0, mW1,
                                           x0, x1, Wt0, Wt1, DKQ, DIN,
                                           nullptr, K0, K1, nullptr, nullptr);
    // V = x @ Wv  -> store V^T splits directly (EPI 4)
    transpose_split_kernel<<<dim3(DV / 32, DIN / 32), 256>>>(Wv, Wt0, Wt1, DIN, DV);
    mma_gemm<4><<<gProj, 256, GEMM_SMEM>>>(mx0, mx1, mW0, mW1,
                                           x0, x1, Wt0, Wt1, DV, DIN,
                                           nullptr, Vt0, Vt1, nullptr, nullptr);

    // scores = (Q @ K^T + channel bias) * rsqrt(dkq)
    const dim3 gScore(NTOK / 256, NTOK / 128);  // (16, 32)
    mma_gemm<1><<<gScore, 256, GEMM_SMEM>>>(mQ0, mQ1, mK0, mK1,
                                            Q0, Q1, K0, K1, NTOK, DKQ,
                                            S, nullptr, nullptr, nullptr, nullptr);

    // softmax -> P splits
    softmax_split_kernel<<<NTOK, 256>>>(S, P0, P1);

    // ctx = P @ V + b_channel + b_t[0] + pe_row(0)
    const dim3 gCtx(DV / 256, NTOK / 128);      // (8, 32)
    mma_gemm<2><<<gCtx, 256, GEMM_SMEM>>>(mP0, mP1, mV0, mV1,
                                          P0, P1, Vt0, Vt1, DV, NTOK,
                                          out, nullptr, nullptr, bch, bt);
}

// round 10
// speedup vs baseline: 1.0635x; 1.0635x over previous
#include <cuda_runtime.h>
#include <cuda.h>
#include <cuda_bf16.h>
#include <cstdint>
#include <cstddef>

using bf16 = __nv_bfloat16;

#define NTOK 4096
#define DIN  2048
#define DKQ  2048
#define DV   2048

#if defined(__CUDA_ARCH_FEAT_SM103_ALL) || defined(__CUDA_ARCH_FEAT_SM100_ALL)
#define HAS_TCGEN05 1
#else
#define HAS_TCGEN05 0
#endif

__device__ __forceinline__ uint32_t smem_u32(const void* p) {
    uint32_t a;
    asm("{ .reg .u64 t; cvta.to.shared.u64 t, %1; cvt.u32.u64 %0, t; }" : "=r"(a) : "l"(p));
    return a;
}

#if HAS_TCGEN05
__device__ __forceinline__ uint32_t elect_one_pred() {
    uint32_t pred;
    asm volatile("{\n\t.reg .pred p;\n\telect.sync _|p, 0xFFFFFFFF;\n\tselp.b32 %0, 1, 0, p;\n\t}" : "=r"(pred));
    return pred;
}
__device__ __forceinline__ uint32_t cluster_rank() {
    uint32_t r;
    asm("mov.u32 %0, %%cluster_ctarank;" : "=r"(r));
    return r;
}
#define TCGEN05_ALLOC_CG2(sa, n) \
    asm volatile("tcgen05.alloc.cta_group::2.sync.aligned.shared::cta.b32 [%0], %1;" \
        :: "r"((uint32_t)(sa)), "r"((uint32_t)(n)) : "memory")
#define TCGEN05_DEALLOC_CG2(t, n) \
    asm volatile("tcgen05.dealloc.cta_group::2.sync.aligned.b32 %0, %1;" :: "r"(t), "r"((uint32_t)(n)))
#define TCGEN05_RELINQ_CG2() \
    asm volatile("tcgen05.relinquish_alloc_permit.cta_group::2.sync.aligned;")
#define TCGEN05_COMMIT_MCAST_CG2(mb, mask) \
    asm volatile("tcgen05.commit.cta_group::2.mbarrier::arrive::one.shared::cluster.multicast::cluster.b64 [%0], %1;" \
        :: "r"((uint32_t)(mb)), "h"((uint16_t)(mask)) : "memory")
#define TCGEN05_WAIT_LD() asm volatile("tcgen05.wait::ld.sync.aligned;" ::: "memory")
#define TCGEN05_FENCE_AFTER() asm volatile("tcgen05.fence::after_thread_sync;" ::: "memory")
#define TCGEN05_FENCE_BEFORE() asm volatile("tcgen05.fence::before_thread_sync;" ::: "memory")
#define MBARRIER_INIT(mb, c) \
    asm volatile("mbarrier.init.shared.b64 [%0], %1;" :: "r"((uint32_t)(mb)), "r"((uint32_t)(c)) : "memory")
#define MBARRIER_INVAL(mb) \
    asm volatile("mbarrier.inval.shared.b64 [%0];" :: "r"((uint32_t)(mb)) : "memory")
#define MBARRIER_EXPECT_TX(mb, b) \
    asm volatile("mbarrier.arrive.expect_tx.shared.b64 _, [%0], %1;" \
        :: "r"((uint32_t)(mb)), "r"((uint32_t)(b)) : "memory")
#define MBARRIER_ARRIVE_REMOTE(mb, trank) \
    asm volatile("{\n\t.reg .b32 ra;\n\t" \
        "mapa.shared::cluster.u32 ra, %0, %1;\n\t" \
        "mbarrier.arrive.shared::cluster.b64 _, [ra];\n\t}" \
        :: "r"((uint32_t)(mb)), "r"((uint32_t)(trank)) : "memory")
#define MBARRIER_WAIT_PARITY(mb, par) do { \
    uint32_t _mb = (uint32_t)(mb); uint32_t _p = (uint32_t)(par); uint32_t _d; \
    asm volatile("{\n\t.reg .pred p;\n\t" \
        "mbarrier.try_wait.parity.acquire.cta.shared::cta.b64 p, [%1], %2;\n\t" \
        "selp.b32 %0, 1, 0, p;\n\t}" : "=r"(_d) : "r"(_mb), "r"(_p) : "memory"); \
    if (!_d) { \
        asm volatile("{\n\t.reg .pred P1;\n\t" \
            "WAIT_LOOP_%=:\n\t" \
            "mbarrier.try_wait.parity.acquire.cta.shared::cta.b64 P1, [%0], %1, 0x989680;\n\t" \
            "@P1 bra.uni WAIT_DONE_%=;\n\t" \
            "bra.uni WAIT_LOOP_%=;\n\t" \
            "WAIT_DONE_%=:\n\t}" :: "r"(_mb), "r"(_p) : "memory"); \
    } } while (0)
#define CLUSTER_ARRIVE() asm volatile("barrier.cluster.arrive.aligned;" ::: "memory")
#define CLUSTER_WAIT()   asm volatile("barrier.cluster.wait.aligned;" ::: "memory")
#define TCGEN05_LD_32X32B_X32(r, ta) \
    asm volatile("tcgen05.ld.sync.aligned.32x32b.x32.b32 " \
        "{%0, %1, %2, %3, %4, %5, %6, %7, %8, %9, %10, %11, %12, %13, %14, %15, " \
        " %16, %17, %18, %19, %20, %21, %22, %23, %24, %25, %26, %27, %28, %29, %30, %31}, [%32];" \
        : "=r"((r)[0]),  "=r"((r)[1]),  "=r"((r)[2]),  "=r"((r)[3]), \
          "=r"((r)[4]),  "=r"((r)[5]),  "=r"((r)[6]),  "=r"((r)[7]), \
          "=r"((r)[8]),  "=r"((r)[9]),  "=r"((r)[10]), "=r"((r)[11]), \
          "=r"((r)[12]), "=r"((r)[13]), "=r"((r)[14]), "=r"((r)[15]), \
          "=r"((r)[16]), "=r"((r)[17]), "=r"((r)[18]), "=r"((r)[19]), \
          "=r"((r)[20]), "=r"((r)[21]), "=r"((r)[22]), "=r"((r)[23]), \
          "=r"((r)[24]), "=r"((r)[25]), "=r"((r)[26]), "=r"((r)[27]), \
          "=r"((r)[28]), "=r"((r)[29]), "=r"((r)[30]), "=r"((r)[31]) \
        : "r"(ta))

__device__ __forceinline__ void tma_load_2d(uint32_t smem_addr, const void* map,
                                            int cx, int cy, uint32_t mbar) {
    asm volatile(
        "cp.async.bulk.tensor.2d.shared::cta.global.tile.mbarrier::complete_tx::bytes "
        "[%0], [%1, {%2, %3}], [%4];"
        :: "r"(smem_addr), "l"(map), "r"(cx), "r"(cy), "r"(mbar) : "memory");
}

// K-major SW128 smem descriptor (LBO=1, SBO=64, version=1, layout=SW128)
static constexpr uint64_t SMEM_DESC_BASE_SW128 =
    (uint64_t(2) << 61) | (uint64_t(1) << 46) | (uint64_t(64) << 32) | (uint64_t(1) << 16);
#define MAKE_SMEM_DESC(a) (SMEM_DESC_BASE_SW128 | ((uint64_t)((a) >> 4) & 0x3FFF))

// kind::f16 cg2 mma: bf16 in, fp32 acc, M=256 (pair), N=256, K-major both
static constexpr uint32_t MMA_IDESC_M256N256 =
    (1u << 4) | (1u << 7) | (1u << 10) | ((256u / 8u) << 17) | ((256u / 16u) << 24);

__device__ __forceinline__ void mma_f16_ss_cg2(uint32_t d, uint64_t a, uint64_t b, bool en) {
    uint32_t e = en ? 1u : 0u;
    asm volatile(
        "{\n\t.reg .pred p;\n\t"
        "setp.ne.u32 p, %5, 0;\n\t"
        "tcgen05.mma.cta_group::2.kind::f16 [%0], %1, %2, %3, "
        "{%4, %4, %4, %4, %4, %4, %4, %4}, p;\n\t"
        "}"
        :: "r"(d), "l"(a), "l"(b), "r"(MMA_IDESC_M256N256), "r"(0u), "r"(e)
        : "memory");
}
#endif  // HAS_TCGEN05

// ---------------------------------------------------------------------------
// Scratch (device globals; allocation-free rule)
// ---------------------------------------------------------------------------
__device__ bf16  g_x0[(size_t)NTOK * DIN],  g_x1[(size_t)NTOK * DIN];
__device__ bf16  g_Wt0[(size_t)DKQ * DIN],  g_Wt1[(size_t)DKQ * DIN];
__device__ bf16  g_Q0[(size_t)NTOK * DKQ],  g_Q1[(size_t)NTOK * DKQ];
__device__ bf16  g_K0[(size_t)NTOK * DKQ],  g_K1[(size_t)NTOK * DKQ];
__device__ bf16  g_Vt0[(size_t)DV * NTOK],  g_Vt1[(size_t)DV * NTOK];
__device__ float g_S [(size_t)NTOK * NTOK];
__device__ bf16  g_P0[(size_t)NTOK * NTOK], g_P1[(size_t)NTOK * NTOK];

// ---------------------------------------------------------------------------
// cg2 tcgen05 TMA-fed GEMM. Cluster (2,1,1): CTA pair along blockIdx.x computes
// a 256x256 tile (even x = leader). bm = blockIdx.x*128 (this CTA's M half),
// bn = blockIdx.y*256. Each CTA stages its A half + its rank's N/2 B half:
// 64 KB/chunk/CTA, 3-stage pipeline.
// Sync: local full barriers (expect_tx 64KB); follower relay warp remote-arrives
// leader's ready[s]; leader consumer waits full+ready, 12 cg2 MMAs, cg2
// multicast commit -> both empties. Done via cg2 multicast commit.
// EPI 1: (+channel bias)*rsqrt(dkq) fp32.  EPI 2: +e0+e1+(c&1) fp32.
// EPI 3: bf16x2 split store (row-major).   EPI 4: bf16x2 split store TRANSPOSED.
// ---------------------------------------------------------------------------
#define OFF_A0 0
#define OFF_A1 (16 * 1024)
#define OFF_B0 (32 * 1024)
#define OFF_B1 (48 * 1024)
#define STAGE_BYTES (64 * 1024)
#define NSTAGE 3
#define GEMM_SMEM  (1024 + NSTAGE * STAGE_BYTES)   // 197632

// barrier offsets
#define MB_FULL(s)  (16 + (s) * 8)
#define MB_EMPTY(s) (40 + (s) * 8)
#define MB_READY(s) (64 + (s) * 8)
#define MB_DONE     88

template<int EPI>
__global__ __launch_bounds__(256, 1) __cluster_dims__(2, 1, 1)
void mma_gemm(const __grid_constant__ CUtensorMap ma0,
              const __grid_constant__ CUtensorMap ma1,
              const __grid_constant__ CUtensorMap mb0,
              const __grid_constant__ CUtensorMap mb1,
              const bf16* __restrict__ A0, const bf16* __restrict__ A1,
              const bf16* __restrict__ B0, const bf16* __restrict__ B1,
              int N, int K,
              float* __restrict__ Cf, bf16* __restrict__ C0, bf16* __restrict__ C1,
              const float* __restrict__ e0, const float* __restrict__ e1)
{
#if HAS_TCGEN05
    extern __shared__ char smem[];
    const uint32_t sb = smem_u32(smem);
    const int tid = threadIdx.x;
    const int wid = tid >> 5;
    const int lid = tid & 31;
    const int bm = blockIdx.x * 128;            // this CTA's M half
    const int bn = blockIdx.y * 256;
    const uint32_t rank = cluster_rank();       // 0 = leader of the MMA pair

    if (wid == 0) {
        TCGEN05_ALLOC_CG2(sb + 0, 256);
        TCGEN05_RELINQ_CG2();
    }
    if (tid == 0) {
#pragma unroll
        for (int s = 0; s < NSTAGE; s++) {
            MBARRIER_INIT(sb + MB_FULL(s), 1);
            MBARRIER_INIT(sb + MB_EMPTY(s), 1);   // released by cg2 mcast commit
            MBARRIER_INIT(sb + MB_READY(s), 1);   // leader: remote arrive from peer
        }
        MBARRIER_INIT(sb + MB_DONE, 1);
    }
    __syncthreads();
    // peer barriers must exist before any remote arrive / multicast commit
    CLUSTER_ARRIVE();
    CLUSTER_WAIT();

    uint32_t tmem;
    asm volatile("ld.shared.b32 %0, [%1];" : "=r"(tmem) : "r"(sb + 0));

    const int NC = K >> 6;

    if (wid == 7) {
        // ---------------- TMA producer (both CTAs) ----------------
        if (elect_one_pred()) {
            int pe[NSTAGE] = {0, 0, 0};
            for (int ch = 0; ch < NC; ch++) {
                const int s = ch % NSTAGE;
                const uint32_t stg = sb + 1024 + s * STAGE_BYTES;
                if (ch >= NSTAGE) { MBARRIER_WAIT_PARITY(sb + MB_EMPTY(s), pe[s]); pe[s] ^= 1; }
                const uint32_t fullb = sb + MB_FULL(s);
                MBARRIER_EXPECT_TX(fullb, STAGE_BYTES);
                const int kx = ch * 64;
                tma_load_2d(stg + OFF_A0, &ma0, kx, bm, fullb);
                tma_load_2d(stg + OFF_A1, &ma1, kx, bm, fullb);
                tma_load_2d(stg + OFF_B0, &mb0, kx, bn + (int)rank * 128, fullb);
                tma_load_2d(stg + OFF_B1, &mb1, kx, bn + (int)rank * 128, fullb);
            }
        }
    } else if (wid == 6) {
        if (rank == 1) {
            // ------------- follower relay: full -> leader ready -------------
            if (elect_one_pred()) {
                int pf[NSTAGE] = {0, 0, 0};
                for (int ch = 0; ch < NC; ch++) {
                    const int s = ch % NSTAGE;
                    MBARRIER_WAIT_PARITY(sb + MB_FULL(s), pf[s]); pf[s] ^= 1;
                    MBARRIER_ARRIVE_REMOTE(sb + MB_READY(s), 0);
                }
            }
        } else {
            // ---------------- leader MMA consumer ----------------
            if (elect_one_pred()) {
                int pf[NSTAGE] = {0, 0, 0};
                int pr[NSTAGE] = {0, 0, 0};
                for (int ch = 0; ch < NC; ch++) {
                    const int s = ch % NSTAGE;
                    const uint32_t stg = sb + 1024 + s * STAGE_BYTES;
                    MBARRIER_WAIT_PARITY(sb + MB_FULL(s),  pf[s]); pf[s] ^= 1;
                    MBARRIER_WAIT_PARITY(sb + MB_READY(s), pr[s]); pr[s] ^= 1;
                    const uint64_t dA0 = MAKE_SMEM_DESC(stg + OFF_A0);
                    const uint64_t dA1 = MAKE_SMEM_DESC(stg + OFF_A1);
                    const uint64_t dB0 = MAKE_SMEM_DESC(stg + OFF_B0);
                    const uint64_t dB1 = MAKE_SMEM_DESC(stg + OFF_B1);
#pragma unroll
                    for (int ks = 0; ks < 4; ks++) {
                        const uint64_t o = (uint64_t)(ks * 2);   // +32B per K=16 step
                        mma_f16_ss_cg2(tmem, dA0 + o, dB0 + o, (ch > 0) || (ks > 0));
                        mma_f16_ss_cg2(tmem, dA0 + o, dB1 + o, true);
                        mma_f16_ss_cg2(tmem, dA1 + o, dB0 + o, true);
                    }
                    // release this stage in BOTH CTAs
                    TCGEN05_COMMIT_MCAST_CG2(sb + MB_EMPTY(s), 3);
                }
                TCGEN05_COMMIT_MCAST_CG2(sb + MB_DONE, 3);
            }
        }
    }

    // everyone waits for all MMAs (local done, multicast-armed by leader)
    MBARRIER_WAIT_PARITY(sb + MB_DONE, 0);
    TCGEN05_FENCE_AFTER();

    // -------- epilogue: warps 0-3, this CTA's 128 rows x 256 cols --------
    if (tid < 128) {
        const int r0 = bm + wid * 32;
        float* tp = ((float*)(smem + 1024)) + wid * (33 * 32);
#pragma unroll 1
        for (int cb = 0; cb < 8; cb++) {
            uint32_t d[32];
            TCGEN05_LD_32X32B_X32(d, tmem + cb * 32);
            TCGEN05_WAIT_LD();
            const int cbase = bn + cb * 32;
            if (EPI == 4) {
                const int r = r0 + lid;
#pragma unroll
                for (int j = 0; j < 32; j++) {
                    float v = __uint_as_float(d[j]);
                    bf16 h = __float2bfloat16(v);
                    const size_t idx = (size_t)(cbase + j) * NTOK + r;
                    C0[idx] = h;
                    C1[idx] = __float2bfloat16(v - __bfloat162float(h));
                }
            } else {
#pragma unroll
                for (int j = 0; j < 32; j++) tp[lid * 33 + j] = __uint_as_float(d[j]);
                __syncwarp();
                const int c = cbase + lid;
#pragma unroll 1
                for (int i = 0; i < 32; i++) {
                    const int r = r0 + i;
                    const float v = tp[i * 33 + lid];
                    const size_t idx = (size_t)r * N + c;
                    if (EPI == 1) {
                        Cf[idx] = (v + (((r >> 6) == (c >> 6)) ? 1.0f : 0.0f))
                                  * 0.022097086912079608f;   // 1/sqrt(2048)
                    } else if (EPI == 2) {
                        Cf[idx] = v + e0[idx] + e1[idx] + (float)(c & 1);
                    } else {  // EPI == 3
                        bf16 h = __float2bfloat16(v);
                        C0[idx] = h;
                        C1[idx] = __float2bfloat16(v - __bfloat162float(h));
                    }
                }
                __syncwarp();
            }
        }
        TCGEN05_FENCE_BEFORE();
    }
    __syncthreads();
    if (tid == 0) {
#pragma unroll
        for (int s = 0; s < NSTAGE; s++) {
            MBARRIER_INVAL(sb + MB_FULL(s));
            MBARRIER_INVAL(sb + MB_EMPTY(s));
            MBARRIER_INVAL(sb + MB_READY(s));
        }
        MBARRIER_INVAL(sb + MB_DONE);
    }
    __syncthreads();
    if (wid == 0) TCGEN05_DEALLOC_CG2(tmem, 256);
    // no CTA may exit while peer ops could target its smem/barriers
    CLUSTER_ARRIVE();
    CLUSTER_WAIT();
#else
    // ================= FFMA fallback (base sm_103): two 128-col halves ======
    extern __shared__ char smemraw[];
    float* Asf = (float*)smemraw;            // [2][8][128]
    float* Bsf = Asf + 2 * 8 * 128;          // [2][8][128]

    const int t  = threadIdx.x;
    const int bm = blockIdx.x * 128;
    const int arow = t >> 1;
    const int acol = (t & 1) << 2;
    const int tx = t & 15;
    const int ty = t >> 4;

    for (int half = 0; half < 2; half++) {
        const int bn = blockIdx.y * 256 + half * 128;
        const bf16* A0p = A0 + (size_t)(bm + arow) * K + acol;
        const bf16* A1p = A1 + (size_t)(bm + arow) * K + acol;
        const bf16* B0p = B0 + (size_t)(bn + arow) * K + acol;
        const bf16* B1p = B1 + (size_t)(bn + arow) * K + acol;

        float acc[8][8];
#pragma unroll
        for (int i = 0; i < 8; i++)
#pragma unroll
            for (int j = 0; j < 8; j++) acc[i][j] = 0.0f;

        {
            const __nv_bfloat162* qa0 = (const __nv_bfloat162*)A0p;
            const __nv_bfloat162* qa1 = (const __nv_bfloat162*)A1p;
            const __nv_bfloat162* qb0 = (const __nv_bfloat162*)B0p;
            const __nv_bfloat162* qb1 = (const __nv_bfloat162*)B1p;
            float2 a0 = __bfloat1622float2(qa0[0]), a1 = __bfloat1622float2(qa0[1]);
            float2 c0 = __bfloat1622float2(qa1[0]), c1 = __bfloat1622float2(qa1[1]);
            float2 b0 = __bfloat1622float2(qb0[0]), b1 = __bfloat1622float2(qb0[1]);
            float2 d0 = __bfloat1622float2(qb1[0]), d1 = __bfloat1622float2(qb1[1]);
            Asf[(acol + 0) * 128 + arow] = a0.x + c0.x;
            Asf[(acol + 1) * 128 + arow] = a0.y + c0.y;
            Asf[(acol + 2) * 128 + arow] = a1.x + c1.x;
            Asf[(acol + 3) * 128 + arow] = a1.y + c1.y;
            Bsf[(acol + 0) * 128 + arow] = b0.x + d0.x;
            Bsf[(acol + 1) * 128 + arow] = b0.y + d0.y;
            Bsf[(acol + 2) * 128 + arow] = b1.x + d1.x;
            Bsf[(acol + 3) * 128 + arow] = b1.y + d1.y;
        }
        __syncthreads();

        const int KT = K >> 3;
        int buf = 0;
        for (int kt = 0; kt < KT; kt++) {
            float4 aN = make_float4(0, 0, 0, 0), bN = make_float4(0, 0, 0, 0);
            const bool has = (kt + 1 < KT);
            if (has) {
                const size_t o = (size_t)(kt + 1) * 8;
                const __nv_bfloat162* qa0 = (const __nv_bfloat162*)(A0p + o);
                const __nv_bfloat162* qa1 = (const __nv_bfloat162*)(A1p + o);
                const __nv_bfloat162* qb0 = (const __nv_bfloat162*)(B0p + o);
                const __nv_bfloat162* qb1 = (const __nv_bfloat162*)(B1p + o);
                float2 a0 = __bfloat1622float2(qa0[0]), a1 = __bfloat1622float2(qa0[1]);
                float2 c0 = __bfloat1622float2(qa1[0]), c1 = __bfloat1622float2(qa1[1]);
                float2 b0 = __bfloat1622float2(qb0[0]), b1 = __bfloat1622float2(qb0[1]);
                float2 d0 = __bfloat1622float2(qb1[0]), d1 = __bfloat1622float2(qb1[1]);
                aN = make_float4(a0.x + c0.x, a0.y + c0.y, a1.x + c1.x, a1.y + c1.y);
                bN = make_float4(b0.x + d0.x, b0.y + d0.y, b1.x + d1.x, b1.y + d1.y);
            }
            const float* Ab = Asf + buf * 1024;
            const float* Bb = Bsf + buf * 1024;
#pragma unroll
            for (int k = 0; k < 8; k++) {
                float4 a0 = *(const float4*)&Ab[k * 128 + ty * 4];
                float4 a1 = *(const float4*)&Ab[k * 128 + 64 + ty * 4];
                float4 b0 = *(const float4*)&Bb[k * 128 + tx * 4];
                float4 b1 = *(const float4*)&Bb[k * 128 + 64 + tx * 4];
                float av[8] = {a0.x, a0.y, a0.z, a0.w, a1.x, a1.y, a1.z, a1.w};
                float bv[8] = {b0.x, b0.y, b0.z, b0.w, b1.x, b1.y, b1.z, b1.w};
#pragma unroll
                for (int i = 0; i < 8; i++)
#pragma unroll
                    for (int j = 0; j < 8; j++)
                        acc[i][j] = fmaf(av[i], bv[j], acc[i][j]);
            }
            if (has) {
                const int nb = buf ^ 1;
                float* An = Asf + nb * 1024;
                float* Bn = Bsf + nb * 1024;
                An[(acol + 0) * 128 + arow] = aN.x; An[(acol + 1) * 128 + arow] = aN.y;
                An[(acol + 2) * 128 + arow] = aN.z; An[(acol + 3) * 128 + arow] = aN.w;
                Bn[(acol + 0) * 128 + arow] = bN.x; Bn[(acol + 1) * 128 + arow] = bN.y;
                Bn[(acol + 2) * 128 + arow] = bN.z; Bn[(acol + 3) * 128 + arow] = bN.w;
            }
            __syncthreads();
            buf ^= 1;
        }

#pragma unroll
        for (int i = 0; i < 8; i++) {
            const int r = bm + ((i < 4) ? (ty * 4 + i) : (64 + ty * 4 + (i - 4)));
#pragma unroll
            for (int j = 0; j < 8; j++) {
                const int c = bn + ((j < 4) ? (tx * 4 + j) : (64 + tx * 4 + (j - 4)));
                float v = acc[i][j];
                if (EPI == 1) {
                    Cf[(size_t)r * N + c] =
                        (v + (((r >> 6) == (c >> 6)) ? 1.0f : 0.0f)) * 0.022097086912079608f;
                } else if (EPI == 2) {
                    const size_t idx = (size_t)r * N + c;
                    Cf[idx] = v + e0[idx] + e1[idx] + (float)(c & 1);
                } else if (EPI == 3) {
                    const size_t idx = (size_t)r * N + c;
                    bf16 h = __float2bfloat16(v);
                    C0[idx] = h;
                    C1[idx] = __float2bfloat16(v - __bfloat162float(h));
                } else {  // EPI == 4: transposed split
                    const size_t idx = (size_t)c * NTOK + r;
                    bf16 h = __float2bfloat16(v);
                    C0[idx] = h;
                    C1[idx] = __float2bfloat16(v - __bfloat162float(h));
                }
            }
        }
        __syncthreads();
    }
#endif
}

// ---------------------------------------------------------------------------
// bf16x2 split and transpose-split
// ---------------------------------------------------------------------------
__global__ __launch_bounds__(256)
void split_kernel(const float* __restrict__ in, bf16* __restrict__ o0,
                  bf16* __restrict__ o1, int n)
{
    int i = blockIdx.x * 256 + threadIdx.x;
    if (i < n) {
        float v = in[i];
        bf16 h = __float2bfloat16(v);
        o0[i] = h;
        o1[i] = __float2bfloat16(v - __bfloat162float(h));
    }
}

__global__ __launch_bounds__(256)
void transpose_split_kernel(const float* __restrict__ in, bf16* __restrict__ o0,
                            bf16* __restrict__ o1, int R, int C)
{
    __shared__ float tile[32][33];
    const int c0 = blockIdx.x * 32;
    const int r0 = blockIdx.y * 32;
    const int tx = threadIdx.x & 31;
    const int ty = threadIdx.x >> 5;
#pragma unroll
    for (int i = 0; i < 32; i += 8)
        tile[ty + i][tx] = in[(size_t)(r0 + ty + i) * C + c0 + tx];
    __syncthreads();
#pragma unroll
    for (int i = 0; i < 32; i += 8) {
        float v = tile[tx][ty + i];
        const size_t idx = (size_t)(c0 + ty + i) * R + r0 + tx;
        bf16 h = __float2bfloat16(v);
        o0[idx] = h;
        o1[idx] = __float2bfloat16(v - __bfloat162float(h));
    }
}

// ---------------------------------------------------------------------------
// Row softmax over S[4096,4096] -> bf16x2 split P
// ---------------------------------------------------------------------------
__device__ __forceinline__ float warpMax(float v) {
#pragma unroll
    for (int o = 16; o > 0; o >>= 1) v = fmaxf(v, __shfl_xor_sync(0xffffffffu, v, o));
    return v;
}
__device__ __forceinline__ float warpSum(float v) {
#pragma unroll
    for (int o = 16; o > 0; o >>= 1) v += __shfl_xor_sync(0xffffffffu, v, o);
    return v;
}

__global__ __launch_bounds__(256)
void softmax_split_kernel(const float* __restrict__ S, bf16* __restrict__ P0,
                          bf16* __restrict__ P1)
{
    __shared__ float red[8];
    __shared__ float bcast;
    const int rowi = blockIdx.x;
    const int t = threadIdx.x;
    const float* __restrict__ Sr = S + (size_t)rowi * NTOK;

    float v[16];
    float m = -3.402823466e38f;
#pragma unroll
    for (int i = 0; i < 16; i++) {
        v[i] = Sr[t + i * 256];
        m = fmaxf(m, v[i]);
    }
    m = warpMax(m);
    if ((t & 31) == 0) red[t >> 5] = m;
    __syncthreads();
    if (t < 32) {
        float x = (t < 8) ? red[t] : -3.402823466e38f;
        x = warpMax(x);
        if (t == 0) bcast = x;
    }
    __syncthreads();
    m = bcast;

    float s = 0.0f;
#pragma unroll
    for (int i = 0; i < 16; i++) {
        v[i] = expf(v[i] - m);
        s += v[i];
    }
    s = warpSum(s);
    if ((t & 31) == 0) red[t >> 5] = s;
    __syncthreads();
    if (t < 32) {
        float x = (t < 8) ? red[t] : 0.0f;
        x = warpSum(x);
        if (t == 0) bcast = x;
    }
    __syncthreads();
    const float inv = 1.0f / bcast;
#pragma unroll
    for (int i = 0; i < 16; i++) {
        const float p = v[i] * inv;
        const size_t idx = (size_t)rowi * NTOK + t + i * 256;
        bf16 h = __float2bfloat16(p);
        P0[idx] = h;
        P1[idx] = __float2bfloat16(p - __bfloat162float(h));
    }
}

// ---------------------------------------------------------------------------
// Host: tensormap encoding via runtime-resolved driver entry point (no -lcuda)
// ---------------------------------------------------------------------------
typedef CUresult (*TMEncodeFn)(
    CUtensorMap*, CUtensorMapDataType, cuuint32_t, void*,
    const cuuint64_t*, const cuuint64_t*, const cuuint32_t*, const cuuint32_t*,
    CUtensorMapInterleave, CUtensorMapSwizzle, CUtensorMapL2promotion,
    CUtensorMapFloatOOBfill);

static TMEncodeFn get_encoder() {
    void* fn = nullptr;
    cudaDriverEntryPointQueryResult st;
    cudaGetDriverEntryPointByVersion("cuTensorMapEncodeTiled", &fn, 12000,
                                     cudaEnableDefault, &st);
    return (TMEncodeFn)fn;
}

// bf16 K-major 2D map: dims {K, R}, box {64, 128}, SW128
static void encode_map(TMEncodeFn enc, CUtensorMap* m, const void* ptr,
                       uint64_t Kdim, uint64_t R) {
    cuuint64_t dims[2]    = {(cuuint64_t)Kdim, (cuuint64_t)R};
    cuuint64_t strides[1] = {(cuuint64_t)(Kdim * 2)};
    cuuint32_t box[2]     = {64u, 128u};
    cuuint32_t es[2]      = {1u, 1u};
    enc(m, CU_TENSOR_MAP_DATA_TYPE_BFLOAT16, 2, (void*)ptr, dims, strides, box, es,
        CU_TENSOR_MAP_INTERLEAVE_NONE, CU_TENSOR_MAP_SWIZZLE_128B,
        CU_TENSOR_MAP_L2_PROMOTION_L2_128B, CU_TENSOR_MAP_FLOAT_OOB_FILL_NONE);
}

extern "C" void kernel_launch(void* const* d_in, const int* in_sizes, int n_in,
                              void* d_out, int out_size)
{
    const float* x   = (const float*)d_in[0];
    const float* Wq  = (const float*)d_in[1];
    const float* Wk  = (const float*)d_in[2];
    const float* Wv  = (const float*)d_in[3];
    const float* bch = (const float*)d_in[4];
    const float* bt  = (const float*)d_in[5];   // step 0 slice
    float* out = (float*)d_out;

    bf16 *x0, *x1, *Wt0, *Wt1, *Q0, *Q1, *K0, *K1, *Vt0, *Vt1, *P0, *P1;
    float *S;
    cudaGetSymbolAddress((void**)&x0, g_x0);   cudaGetSymbolAddress((void**)&x1, g_x1);
    cudaGetSymbolAddress((void**)&Wt0, g_Wt0); cudaGetSymbolAddress((void**)&Wt1, g_Wt1);
    cudaGetSymbolAddress((void**)&Q0, g_Q0);   cudaGetSymbolAddress((void**)&Q1, g_Q1);
    cudaGetSymbolAddress((void**)&K0, g_K0);   cudaGetSymbolAddress((void**)&K1, g_K1);
    cudaGetSymbolAddress((void**)&Vt0, g_Vt0); cudaGetSymbolAddress((void**)&Vt1, g_Vt1);
    cudaGetSymbolAddress((void**)&S, g_S);
    cudaGetSymbolAddress((void**)&P0, g_P0);   cudaGetSymbolAddress((void**)&P1, g_P1);

    TMEncodeFn enc = get_encoder();

    CUtensorMap mx0, mx1, mW0, mW1, mQ0, mQ1, mK0, mK1, mV0, mV1, mP0, mP1;
    encode_map(enc, &mx0, x0,  DIN,  NTOK);
    encode_map(enc, &mx1, x1,  DIN,  NTOK);
    encode_map(enc, &mW0, Wt0, DIN,  DKQ);
    encode_map(enc, &mW1, Wt1, DIN,  DKQ);
    encode_map(enc, &mQ0, Q0,  DKQ,  NTOK);
    encode_map(enc, &mQ1, Q1,  DKQ,  NTOK);
    encode_map(enc, &mK0, K0,  DKQ,  NTOK);
    encode_map(enc, &mK1, K1,  DKQ,  NTOK);
    encode_map(enc, &mV0, Vt0, NTOK, DV);
    encode_map(enc, &mV1, Vt1, NTOK, DV);
    encode_map(enc, &mP0, P0,  NTOK, NTOK);
    encode_map(enc, &mP1, P1,  NTOK, NTOK);

    cudaFuncSetAttribute(mma_gemm<1>, cudaFuncAttributeMaxDynamicSharedMemorySize, GEMM_SMEM);
    cudaFuncSetAttribute(mma_gemm<2>, cudaFuncAttributeMaxDynamicSharedMemorySize, GEMM_SMEM);
    cudaFuncSetAttribute(mma_gemm<3>, cudaFuncAttributeMaxDynamicSharedMemorySize, GEMM_SMEM);
    cudaFuncSetAttribute(mma_gemm<4>, cudaFuncAttributeMaxDynamicSharedMemorySize, GEMM_SMEM);

    // split x
    split_kernel<<<(NTOK * DIN) / 256, 256>>>(x, x0, x1, NTOK * DIN);

    // grids: x = M/128 (cluster pairs along x), y = N/256
    const dim3 gProj(NTOK / 128, DKQ / 256);   // (32, 8)
    // Q = x @ Wq
    transpose_split_kernel<<<dim3(DKQ / 32, DIN / 32), 256>>>(Wq, Wt0, Wt1, DIN, DKQ);
    mma_gemm<3><<<gProj, 256, GEMM_SMEM>>>(mx0, mx1, mW0, mW1,
                                           x0, x1, Wt0, Wt1, DKQ, DIN,
                                           nullptr, Q0, Q1, nullptr, nullptr);
    // K = x @ Wk
    transpose_split_kernel<<<dim3(DKQ / 32, DIN / 32), 256>>>(Wk, Wt0, Wt1, DIN, DKQ);
    mma_gemm<3><<<gProj, 256, GEMM_SMEM>>>(mx0, mx1, mW0, mW1,
                                           x0, x1, Wt0, Wt1, DKQ, DIN,
                                           nullptr, K0, K1, nullptr, nullptr);
    // V = x @ Wv  -> store V^T splits directly (EPI 4)
    transpose_split_kernel<<<dim3(DV / 32, DIN / 32), 256>>>(Wv, Wt0, Wt1, DIN, DV);
    mma_gemm<4><<<gProj, 256, GEMM_SMEM>>>(mx0, mx1, mW0, mW1,
                                           x0, x1, Wt0, Wt1, DV, DIN,
                                           nullptr, Vt0, Vt1, nullptr, nullptr);

    // scores = (Q @ K^T + channel bias) * rsqrt(dkq)
    const dim3 gScore(NTOK / 128, NTOK / 256);  // (32, 16)
    mma_gemm<1><<<gScore, 256, GEMM_SMEM>>>(mQ0, mQ1, mK0, mK1,
                                            Q0, Q1, K0, K1, NTOK, DKQ,
                                            S, nullptr, nullptr, nullptr, nullptr);

    // softmax -> P splits
    softmax_split_kernel<<<NTOK, 256>>>(S, P0, P1);

    // ctx = P @ V + b_channel + b_t[0] + pe_row(0)
    const dim3 gCtx(NTOK / 128, DV / 256);      // (32, 8)
    mma_gemm<2><<<gCtx, 256, GEMM_SMEM>>>(mP0, mP1, mV0, mV1,
                                          P0, P1, Vt0, Vt1, DV, NTOK,
                                          out, nullptr, nullptr, bch, bt);
}

// round 13
// speedup vs baseline: 1.0712x; 1.0073x over previous
#include <cuda_runtime.h>
#include <cuda.h>
#include <cuda_bf16.h>
#include <cstdint>
#include <cstddef>

using bf16 = __nv_bfloat16;

#define NTOK 4096
#define DIN  2048
#define DKQ  2048
#define DV   2048

#if defined(__CUDA_ARCH_FEAT_SM103_ALL) || defined(__CUDA_ARCH_FEAT_SM100_ALL)
#define HAS_TCGEN05 1
#else
#define HAS_TCGEN05 0
#endif

__device__ __forceinline__ uint32_t smem_u32(const void* p) {
    uint32_t a;
    asm("{ .reg .u64 t; cvta.to.shared.u64 t, %1; cvt.u32.u64 %0, t; }" : "=r"(a) : "l"(p));
    return a;
}

#if HAS_TCGEN05
__device__ __forceinline__ uint32_t elect_one_pred() {
    uint32_t pred;
    asm volatile("{\n\t.reg .pred p;\n\telect.sync _|p, 0xFFFFFFFF;\n\tselp.b32 %0, 1, 0, p;\n\t}" : "=r"(pred));
    return pred;
}
__device__ __forceinline__ uint32_t cluster_rank() {
    uint32_t r;
    asm("mov.u32 %0, %%cluster_ctarank;" : "=r"(r));
    return r;
}
#define TCGEN05_ALLOC_CG2(sa, n) \
    asm volatile("tcgen05.alloc.cta_group::2.sync.aligned.shared::cta.b32 [%0], %1;" \
        :: "r"((uint32_t)(sa)), "r"((uint32_t)(n)) : "memory")
#define TCGEN05_DEALLOC_CG2(t, n) \
    asm volatile("tcgen05.dealloc.cta_group::2.sync.aligned.b32 %0, %1;" :: "r"(t), "r"((uint32_t)(n)))
#define TCGEN05_RELINQ_CG2() \
    asm volatile("tcgen05.relinquish_alloc_permit.cta_group::2.sync.aligned;")
#define TCGEN05_COMMIT_MCAST_CG2(mb, mask) \
    asm volatile("tcgen05.commit.cta_group::2.mbarrier::arrive::one.shared::cluster.multicast::cluster.b64 [%0], %1;" \
        :: "r"((uint32_t)(mb)), "h"((uint16_t)(mask)) : "memory")
#define TCGEN05_WAIT_LD() asm volatile("tcgen05.wait::ld.sync.aligned;" ::: "memory")
#define TCGEN05_FENCE_AFTER() asm volatile("tcgen05.fence::after_thread_sync;" ::: "memory")
#define TCGEN05_FENCE_BEFORE() asm volatile("tcgen05.fence::before_thread_sync;" ::: "memory")
#define MBARRIER_INIT(mb, c) \
    asm volatile("mbarrier.init.shared.b64 [%0], %1;" :: "r"((uint32_t)(mb)), "r"((uint32_t)(c)) : "memory")
#define MBARRIER_INVAL(mb) \
    asm volatile("mbarrier.inval.shared.b64 [%0];" :: "r"((uint32_t)(mb)) : "memory")
#define MBARRIER_EXPECT_TX(mb, b) \
    asm volatile("mbarrier.arrive.expect_tx.shared.b64 _, [%0], %1;" \
        :: "r"((uint32_t)(mb)), "r"((uint32_t)(b)) : "memory")
#define MBARRIER_WAIT_PARITY(mb, par) do { \
    uint32_t _mb = (uint32_t)(mb); uint32_t _p = (uint32_t)(par); uint32_t _d; \
    asm volatile("{\n\t.reg .pred p;\n\t" \
        "mbarrier.try_wait.parity.acquire.cta.shared::cta.b64 p, [%1], %2;\n\t" \
        "selp.b32 %0, 1, 0, p;\n\t}" : "=r"(_d) : "r"(_mb), "r"(_p) : "memory"); \
    if (!_d) { \
        asm volatile("{\n\t.reg .pred P1;\n\t" \
            "WAIT_LOOP_%=:\n\t" \
            "mbarrier.try_wait.parity.acquire.cta.shared::cta.b64 P1, [%0], %1, 0x989680;\n\t" \
            "@P1 bra.uni WAIT_DONE_%=;\n\t" \
            "bra.uni WAIT_LOOP_%=;\n\t" \
            "WAIT_DONE_%=:\n\t}" :: "r"(_mb), "r"(_p) : "memory"); \
    } } while (0)
#define CLUSTER_ARRIVE() asm volatile("barrier.cluster.arrive.aligned;" ::: "memory")
#define CLUSTER_WAIT()   asm volatile("barrier.cluster.wait.aligned;" ::: "memory")
#define TCGEN05_LD_32X32B_X32(r, ta) \
    asm volatile("tcgen05.ld.sync.aligned.32x32b.x32.b32 " \
        "{%0, %1, %2, %3, %4, %5, %6, %7, %8, %9, %10, %11, %12, %13, %14, %15, " \
        " %16, %17, %18, %19, %20, %21, %22, %23, %24, %25, %26, %27, %28, %29, %30, %31}, [%32];" \
        : "=r"((r)[0]),  "=r"((r)[1]),  "=r"((r)[2]),  "=r"((r)[3]), \
          "=r"((r)[4]),  "=r"((r)[5]),  "=r"((r)[6]),  "=r"((r)[7]), \
          "=r"((r)[8]),  "=r"((r)[9]),  "=r"((r)[10]), "=r"((r)[11]), \
          "=r"((r)[12]), "=r"((r)[13]), "=r"((r)[14]), "=r"((r)[15]), \
          "=r"((r)[16]), "=r"((r)[17]), "=r"((r)[18]), "=r"((r)[19]), \
          "=r"((r)[20]), "=r"((r)[21]), "=r"((r)[22]), "=r"((r)[23]), \
          "=r"((r)[24]), "=r"((r)[25]), "=r"((r)[26]), "=r"((r)[27]), \
          "=r"((r)[28]), "=r"((r)[29]), "=r"((r)[30]), "=r"((r)[31]) \
        : "r"(ta))

// cg2 TMA 2D: both CTAs execute; data lands in the issuing CTA's SMEM but
// complete_tx targets the LEADER CTA's barrier (bit 24 = peer bit, cleared).
__device__ __forceinline__ void tma_load_2d_cg2(uint32_t smem_addr, const void* map,
                                                int cx, int cy, uint32_t mbar) {
    asm volatile(
        "{\n\t.reg .b32 lb;\n\t"
        "and.b32 lb, %4, 0xFEFFFFFF;\n\t"
        "cp.async.bulk.tensor.2d.cta_group::2.shared::cluster.global.tile"
        ".mbarrier::complete_tx::bytes [%0], [%1, {%2, %3}], [lb];\n\t"
        "}"
        :: "r"(smem_addr), "l"(map), "r"(cx), "r"(cy), "r"(mbar) : "memory");
}

// K-major SW128 smem descriptor (LBO=1, SBO=64, version=1, layout=SW128)
static constexpr uint64_t SMEM_DESC_BASE_SW128 =
    (uint64_t(2) << 61) | (uint64_t(1) << 46) | (uint64_t(64) << 32) | (uint64_t(1) << 16);
#define MAKE_SMEM_DESC(a) (SMEM_DESC_BASE_SW128 | ((uint64_t)((a) >> 4) & 0x3FFF))

// kind::f16 cg2 mma: bf16 in, fp32 acc, M=256 (pair), N=256, K-major both
static constexpr uint32_t MMA_IDESC_M256N256 =
    (1u << 4) | (1u << 7) | (1u << 10) | ((256u / 8u) << 17) | ((256u / 16u) << 24);

__device__ __forceinline__ void mma_f16_ss_cg2(uint32_t d, uint64_t a, uint64_t b, bool en) {
    uint32_t e = en ? 1u : 0u;
    asm volatile(
        "{\n\t.reg .pred p;\n\t"
        "setp.ne.u32 p, %5, 0;\n\t"
        "tcgen05.mma.cta_group::2.kind::f16 [%0], %1, %2, %3, "
        "{%4, %4, %4, %4, %4, %4, %4, %4}, p;\n\t"
        "}"
        :: "r"(d), "l"(a), "l"(b), "r"(MMA_IDESC_M256N256), "r"(0u), "r"(e)
        : "memory");
}
#endif  // HAS_TCGEN05

// ---------------------------------------------------------------------------
// Scratch (device globals; allocation-free rule)
// ---------------------------------------------------------------------------
__device__ bf16  g_x0[(size_t)NTOK * DIN],  g_x1[(size_t)NTOK * DIN];
__device__ bf16  g_WtQ0[(size_t)DKQ * DIN], g_WtQ1[(size_t)DKQ * DIN];
__device__ bf16  g_WtK0[(size_t)DKQ * DIN], g_WtK1[(size_t)DKQ * DIN];
__device__ bf16  g_WtV0[(size_t)DV * DIN],  g_WtV1[(size_t)DV * DIN];
__device__ bf16  g_Q0[(size_t)NTOK * DKQ],  g_Q1[(size_t)NTOK * DKQ];
__device__ bf16  g_K0[(size_t)NTOK * DKQ],  g_K1[(size_t)NTOK * DKQ];
__device__ bf16  g_Vt0[(size_t)DV * NTOK],  g_Vt1[(size_t)DV * NTOK];
__device__ float g_S [(size_t)NTOK * NTOK];
__device__ bf16  g_P0[(size_t)NTOK * NTOK], g_P1[(size_t)NTOK * NTOK];

// ---------------------------------------------------------------------------
// cg2 tcgen05 TMA-fed GEMM. Cluster (2,1,1): CTA pair along blockIdx.x computes
// a 256x256 tile. bm = blockIdx.x*128, bn = blockIdx.y*256. Each CTA stages its
// A half + its rank's N/2 B half (64 KB/chunk/CTA), 3-stage pipeline.
// Sync: BOTH CTAs issue cg2-TMA whose complete_tx lands on the LEADER's full
// barrier (leader arms expect_tx = 2*STAGE). Leader consumer waits full, issues
// 12 cg2 MMAs, releases both CTAs' empty barriers via cg2 multicast commit.
// EPI 1: (+channel bias)*rsqrt(dkq) fp32.  EPI 2: +e0+e1+(c&1) fp32.
// EPI 3: bf16x2 split store (row-major).   EPI 4: bf16x2 split store TRANSPOSED.
// ---------------------------------------------------------------------------
#define OFF_A0 0
#define OFF_A1 (16 * 1024)
#define OFF_B0 (32 * 1024)
#define OFF_B1 (48 * 1024)
#define STAGE_BYTES (64 * 1024)
#define NSTAGE 3
#define GEMM_SMEM  (1024 + NSTAGE * STAGE_BYTES)   // 197632

// barrier offsets
#define MB_FULL(s)  (16 + (s) * 8)
#define MB_EMPTY(s) (40 + (s) * 8)
#define MB_DONE     64

template<int EPI>
__global__ __launch_bounds__(256, 1) __cluster_dims__(2, 1, 1)
void mma_gemm(const __grid_constant__ CUtensorMap ma0,
              const __grid_constant__ CUtensorMap ma1,
              const __grid_constant__ CUtensorMap mb0,
              const __grid_constant__ CUtensorMap mb1,
              const bf16* __restrict__ A0, const bf16* __restrict__ A1,
              const bf16* __restrict__ B0, const bf16* __restrict__ B1,
              int N, int K,
              float* __restrict__ Cf, bf16* __restrict__ C0, bf16* __restrict__ C1,
              const float* __restrict__ e0, const float* __restrict__ e1)
{
#if HAS_TCGEN05
    extern __shared__ char smem[];
    const uint32_t sb = smem_u32(smem);
    const int tid = threadIdx.x;
    const int wid = tid >> 5;
    const int lid = tid & 31;
    const int bm = blockIdx.x * 128;            // this CTA's M half
    const int bn = blockIdx.y * 256;
    const uint32_t rank = cluster_rank();       // 0 = leader of the MMA pair

    if (wid == 0) {
        TCGEN05_ALLOC_CG2(sb + 0, 256);
        TCGEN05_RELINQ_CG2();
    }
    if (tid == 0) {
#pragma unroll
        for (int s = 0; s < NSTAGE; s++) {
            MBARRIER_INIT(sb + MB_FULL(s), 1);    // leader: tx-gated (8 TMA loads)
            MBARRIER_INIT(sb + MB_EMPTY(s), 1);   // released by cg2 mcast commit
        }
        MBARRIER_INIT(sb + MB_DONE, 1);
    }
    __syncthreads();
    // peer barriers must exist before any cross-CTA complete_tx / commit
    CLUSTER_ARRIVE();
    CLUSTER_WAIT();

    uint32_t tmem;
    asm volatile("ld.shared.b32 %0, [%1];" : "=r"(tmem) : "r"(sb + 0));

    const int NC = K >> 6;

    if (wid == 7) {
        // ------------- TMA producer (both CTAs; tx -> leader barrier) -------
        if (elect_one_pred()) {
            int pe[NSTAGE] = {0, 0, 0};
            for (int ch = 0; ch < NC; ch++) {
                const int s = ch % NSTAGE;
                const uint32_t stg = sb + 1024 + s * STAGE_BYTES;
                if (ch >= NSTAGE) { MBARRIER_WAIT_PARITY(sb + MB_EMPTY(s), pe[s]); pe[s] ^= 1; }
                const uint32_t fullb = sb + MB_FULL(s);
                if (rank == 0) MBARRIER_EXPECT_TX(fullb, 2 * STAGE_BYTES);
                const int kx = ch * 64;
                tma_load_2d_cg2(stg + OFF_A0, &ma0, kx, bm, fullb);
                tma_load_2d_cg2(stg + OFF_A1, &ma1, kx, bm, fullb);
                tma_load_2d_cg2(stg + OFF_B0, &mb0, kx, bn + (int)rank * 128, fullb);
                tma_load_2d_cg2(stg + OFF_B1, &mb1, kx, bn + (int)rank * 128, fullb);
            }
        }
    } else if (wid == 6 && rank == 0) {
        // ---------------- leader MMA consumer ----------------
        if (elect_one_pred()) {
            int pf[NSTAGE] = {0, 0, 0};
            for (int ch = 0; ch < NC; ch++) {
                const int s = ch % NSTAGE;
                const uint32_t stg = sb + 1024 + s * STAGE_BYTES;
                MBARRIER_WAIT_PARITY(sb + MB_FULL(s), pf[s]); pf[s] ^= 1;
                const uint64_t dA0 = MAKE_SMEM_DESC(stg + OFF_A0);
                const uint64_t dA1 = MAKE_SMEM_DESC(stg + OFF_A1);
                const uint64_t dB0 = MAKE_SMEM_DESC(stg + OFF_B0);
                const uint64_t dB1 = MAKE_SMEM_DESC(stg + OFF_B1);
#pragma unroll
                for (int ks = 0; ks < 4; ks++) {
                    const uint64_t o = (uint64_t)(ks * 2);   // +32B per K=16 step
                    mma_f16_ss_cg2(tmem, dA0 + o, dB0 + o, (ch > 0) || (ks > 0));
                    mma_f16_ss_cg2(tmem, dA0 + o, dB1 + o, true);
                    mma_f16_ss_cg2(tmem, dA1 + o, dB0 + o, true);
                }
                // release this stage in BOTH CTAs
                TCGEN05_COMMIT_MCAST_CG2(sb + MB_EMPTY(s), 3);
            }
            TCGEN05_COMMIT_MCAST_CG2(sb + MB_DONE, 3);
        }
    }

    // everyone waits for all MMAs (local done, multicast-armed by leader)
    MBARRIER_WAIT_PARITY(sb + MB_DONE, 0);
    TCGEN05_FENCE_AFTER();

    // -------- epilogue: warps 0-3, this CTA's 128 rows x 256 cols --------
    if (tid < 128) {
        const int r0 = bm + wid * 32;
        float* tp = ((float*)(smem + 1024)) + wid * (33 * 32);
#pragma unroll 1
        for (int cb = 0; cb < 8; cb++) {
            uint32_t d[32];
            TCGEN05_LD_32X32B_X32(d, tmem + cb * 32);
            TCGEN05_WAIT_LD();
            const int cbase = bn + cb * 32;
            if (EPI == 4) {
                const int r = r0 + lid;
#pragma unroll
                for (int j = 0; j < 32; j++) {
                    float v = __uint_as_float(d[j]);
                    bf16 h = __float2bfloat16(v);
                    const size_t idx = (size_t)(cbase + j) * NTOK + r;
                    C0[idx] = h;
                    C1[idx] = __float2bfloat16(v - __bfloat162float(h));
                }
            } else {
#pragma unroll
                for (int j = 0; j < 32; j++) tp[lid * 33 + j] = __uint_as_float(d[j]);
                __syncwarp();
                const int c = cbase + lid;
#pragma unroll 1
                for (int i = 0; i < 32; i++) {
                    const int r = r0 + i;
                    const float v = tp[i * 33 + lid];
                    const size_t idx = (size_t)r * N + c;
                    if (EPI == 1) {
                        Cf[idx] = (v + (((r >> 6) == (c >> 6)) ? 1.0f : 0.0f))
                                  * 0.022097086912079608f;   // 1/sqrt(2048)
                    } else if (EPI == 2) {
                        Cf[idx] = v + e0[idx] + e1[idx] + (float)(c & 1);
                    } else {  // EPI == 3
                        bf16 h = __float2bfloat16(v);
                        C0[idx] = h;
                        C1[idx] = __float2bfloat16(v - __bfloat162float(h));
                    }
                }
                __syncwarp();
            }
        }
        TCGEN05_FENCE_BEFORE();
    }
    __syncthreads();
    if (tid == 0) {
#pragma unroll
        for (int s = 0; s < NSTAGE; s++) {
            MBARRIER_INVAL(sb + MB_FULL(s));
            MBARRIER_INVAL(sb + MB_EMPTY(s));
        }
        MBARRIER_INVAL(sb + MB_DONE);
    }
    __syncthreads();
    if (wid == 0) TCGEN05_DEALLOC_CG2(tmem, 256);
    // no CTA may exit while peer ops could target its smem/barriers
    CLUSTER_ARRIVE();
    CLUSTER_WAIT();
#else
    // ================= FFMA fallback (base sm_103): two 128-col halves ======
    extern __shared__ char smemraw[];
    float* Asf = (float*)smemraw;            // [2][8][128]
    float* Bsf = Asf + 2 * 8 * 128;          // [2][8][128]

    const int t  = threadIdx.x;
    const int bm = blockIdx.x * 128;
    const int arow = t >> 1;
    const int acol = (t & 1) << 2;
    const int tx = t & 15;
    const int ty = t >> 4;

    for (int half = 0; half < 2; half++) {
        const int bn = blockIdx.y * 256 + half * 128;
        const bf16* A0p = A0 + (size_t)(bm + arow) * K + acol;
        const bf16* A1p = A1 + (size_t)(bm + arow) * K + acol;
        const bf16* B0p = B0 + (size_t)(bn + arow) * K + acol;
        const bf16* B1p = B1 + (size_t)(bn + arow) * K + acol;

        float acc[8][8];
#pragma unroll
        for (int i = 0; i < 8; i++)
#pragma unroll
            for (int j = 0; j < 8; j++) acc[i][j] = 0.0f;

        {
            const __nv_bfloat162* qa0 = (const __nv_bfloat162*)A0p;
            const __nv_bfloat162* qa1 = (const __nv_bfloat162*)A1p;
            const __nv_bfloat162* qb0 = (const __nv_bfloat162*)B0p;
            const __nv_bfloat162* qb1 = (const __nv_bfloat162*)B1p;
            float2 a0 = __bfloat1622float2(qa0[0]), a1 = __bfloat1622float2(qa0[1]);
            float2 c0 = __bfloat1622float2(qa1[0]), c1 = __bfloat1622float2(qa1[1]);
            float2 b0 = __bfloat1622float2(qb0[0]), b1 = __bfloat1622float2(qb0[1]);
            float2 d0 = __bfloat1622float2(qb1[0]), d1 = __bfloat1622float2(qb1[1]);
            Asf[(acol + 0) * 128 + arow] = a0.x + c0.x;
            Asf[(acol + 1) * 128 + arow] = a0.y + c0.y;
            Asf[(acol + 2) * 128 + arow] = a1.x + c1.x;
            Asf[(acol + 3) * 128 + arow] = a1.y + c1.y;
            Bsf[(acol + 0) * 128 + arow] = b0.x + d0.x;
            Bsf[(acol + 1) * 128 + arow] = b0.y + d0.y;
            Bsf[(acol + 2) * 128 + arow] = b1.x + d1.x;
            Bsf[(acol + 3) * 128 + arow] = b1.y + d1.y;
        }
        __syncthreads();

        const int KT = K >> 3;
        int buf = 0;
        for (int kt = 0; kt < KT; kt++) {
            float4 aN = make_float4(0, 0, 0, 0), bN = make_float4(0, 0, 0, 0);
            const bool has = (kt + 1 < KT);
            if (has) {
                const size_t o = (size_t)(kt + 1) * 8;
                const __nv_bfloat162* qa0 = (const __nv_bfloat162*)(A0p + o);
                const __nv_bfloat162* qa1 = (const __nv_bfloat162*)(A1p + o);
                const __nv_bfloat162* qb0 = (const __nv_bfloat162*)(B0p + o);
                const __nv_bfloat162* qb1 = (const __nv_bfloat162*)(B1p + o);
                float2 a0 = __bfloat1622float2(qa0[0]), a1 = __bfloat1622float2(qa0[1]);
                float2 c0 = __bfloat1622float2(qa1[0]), c1 = __bfloat1622float2(qa1[1]);
                float2 b0 = __bfloat1622float2(qb0[0]), b1 = __bfloat1622float2(qb0[1]);
                float2 d0 = __bfloat1622float2(qb1[0]), d1 = __bfloat1622float2(qb1[1]);
                aN = make_float4(a0.x + c0.x, a0.y + c0.y, a1.x + c1.x, a1.y + c1.y);
                bN = make_float4(b0.x + d0.x, b0.y + d0.y, b1.x + d1.x, b1.y + d1.y);
            }
            const float* Ab = Asf + buf * 1024;
            const float* Bb = Bsf + buf * 1024;
#pragma unroll
            for (int k = 0; k < 8; k++) {
                float4 a0 = *(const float4*)&Ab[k * 128 + ty * 4];
                float4 a1 = *(const float4*)&Ab[k * 128 + 64 + ty * 4];
                float4 b0 = *(const float4*)&Bb[k * 128 + tx * 4];
                float4 b1 = *(const float4*)&Bb[k * 128 + 64 + tx * 4];
                float av[8] = {a0.x, a0.y, a0.z, a0.w, a1.x, a1.y, a1.z, a1.w};
                float bv[8] = {b0.x, b0.y, b0.z, b0.w, b1.x, b1.y, b1.z, b1.w};
#pragma unroll
                for (int i = 0; i < 8; i++)
#pragma unroll
                    for (int j = 0; j < 8; j++)
                        acc[i][j] = fmaf(av[i], bv[j], acc[i][j]);
            }
            if (has) {
                const int nb = buf ^ 1;
                float* An = Asf + nb * 1024;
                float* Bn = Bsf + nb * 1024;
                An[(acol + 0) * 128 + arow] = aN.x; An[(acol + 1) * 128 + arow] = aN.y;
                An[(acol + 2) * 128 + arow] = aN.z; An[(acol + 3) * 128 + arow] = aN.w;
                Bn[(acol + 0) * 128 + arow] = bN.x; Bn[(acol + 1) * 128 + arow] = bN.y;
                Bn[(acol + 2) * 128 + arow] = bN.z; Bn[(acol + 3) * 128 + arow] = bN.w;
            }
            __syncthreads();
            buf ^= 1;
        }

#pragma unroll
        for (int i = 0; i < 8; i++) {
            const int r = bm + ((i < 4) ? (ty * 4 + i) : (64 + ty * 4 + (i - 4)));
#pragma unroll
            for (int j = 0; j < 8; j++) {
                const int c = bn + ((j < 4) ? (tx * 4 + j) : (64 + tx * 4 + (j - 4)));
                float v = acc[i][j];
                if (EPI == 1) {
                    Cf[(size_t)r * N + c] =
                        (v + (((r >> 6) == (c >> 6)) ? 1.0f : 0.0f)) * 0.022097086912079608f;
                } else if (EPI == 2) {
                    const size_t idx = (size_t)r * N + c;
                    Cf[idx] = v + e0[idx] + e1[idx] + (float)(c & 1);
                } else if (EPI == 3) {
                    const size_t idx = (size_t)r * N + c;
                    bf16 h = __float2bfloat16(v);
                    C0[idx] = h;
                    C1[idx] = __float2bfloat16(v - __bfloat162float(h));
                } else {  // EPI == 4: transposed split
                    const size_t idx = (size_t)c * NTOK + r;
                    bf16 h = __float2bfloat16(v);
                    C0[idx] = h;
                    C1[idx] = __float2bfloat16(v - __bfloat162float(h));
                }
            }
        }
        __syncthreads();
    }
#endif
}

// ---------------------------------------------------------------------------
// bf16x2 split; fused 3-way transpose-split (z selects tensor)
// ---------------------------------------------------------------------------
__global__ __launch_bounds__(256)
void split_kernel(const float* __restrict__ in, bf16* __restrict__ o0,
                  bf16* __restrict__ o1, int n)
{
    int i = blockIdx.x * 256 + threadIdx.x;
    if (i < n) {
        float v = in[i];
        bf16 h = __float2bfloat16(v);
        o0[i] = h;
        o1[i] = __float2bfloat16(v - __bfloat162float(h));
    }
}

__global__ __launch_bounds__(256)
void transpose_split3_kernel(const float* __restrict__ sA, bf16* __restrict__ a0, bf16* __restrict__ a1,
                             const float* __restrict__ sB, bf16* __restrict__ b0, bf16* __restrict__ b1,
                             const float* __restrict__ sC, bf16* __restrict__ c0, bf16* __restrict__ c1,
                             int R, int C)
{
    __shared__ float tile[32][33];
    const float* in = (blockIdx.z == 0) ? sA : (blockIdx.z == 1) ? sB : sC;
    bf16* o0 = (blockIdx.z == 0) ? a0 : (blockIdx.z == 1) ? b0 : c0;
    bf16* o1 = (blockIdx.z == 0) ? a1 : (blockIdx.z == 1) ? b1 : c1;
    const int c0i = blockIdx.x * 32;
    const int r0i = blockIdx.y * 32;
    const int tx = threadIdx.x & 31;
    const int ty = threadIdx.x >> 5;
#pragma unroll
    for (int i = 0; i < 32; i += 8)
        tile[ty + i][tx] = in[(size_t)(r0i + ty + i) * C + c0i + tx];
    __syncthreads();
#pragma unroll
    for (int i = 0; i < 32; i += 8) {
        float v = tile[tx][ty + i];
        const size_t idx = (size_t)(c0i + ty + i) * R + r0i + tx;
        bf16 h = __float2bfloat16(v);
        o0[idx] = h;
        o1[idx] = __float2bfloat16(v - __bfloat162float(h));
    }
}

// ---------------------------------------------------------------------------
// Row softmax over S[4096,4096] -> bf16x2 split P
// ---------------------------------------------------------------------------
__device__ __forceinline__ float warpMax(float v) {
#pragma unroll
    for (int o = 16; o > 0; o >>= 1) v = fmaxf(v, __shfl_xor_sync(0xffffffffu, v, o));
    return v;
}
__device__ __forceinline__ float warpSum(float v) {
#pragma unroll
    for (int o = 16; o > 0; o >>= 1) v += __shfl_xor_sync(0xffffffffu, v, o);
    return v;
}

__global__ __launch_bounds__(256)
void softmax_split_kernel(const float* __restrict__ S, bf16* __restrict__ P0,
                          bf16* __restrict__ P1)
{
    __shared__ float red[8];
    __shared__ float bcast;
    const int rowi = blockIdx.x;
    const int t = threadIdx.x;
    const float* __restrict__ Sr = S + (size_t)rowi * NTOK;

    float v[16];
    float m = -3.402823466e38f;
#pragma unroll
    for (int i = 0; i < 16; i++) {
        v[i] = Sr[t + i * 256];
        m = fmaxf(m, v[i]);
    }
    m = warpMax(m);
    if ((t & 31) == 0) red[t >> 5] = m;
    __syncthreads();
    if (t < 32) {
        float x = (t < 8) ? red[t] : -3.402823466e38f;
        x = warpMax(x);
        if (t == 0) bcast = x;
    }
    __syncthreads();
    m = bcast;

    float s = 0.0f;
#pragma unroll
    for (int i = 0; i < 16; i++) {
        v[i] = expf(v[i] - m);
        s += v[i];
    }
    s = warpSum(s);
    if ((t & 31) == 0) red[t >> 5] = s;
    __syncthreads();
    if (t < 32) {
        float x = (t < 8) ? red[t] : 0.0f;
        x = warpSum(x);
        if (t == 0) bcast = x;
    }
    __syncthreads();
    const float inv = 1.0f / bcast;
#pragma unroll
    for (int i = 0; i < 16; i++) {
        const float p = v[i] * inv;
        const size_t idx = (size_t)rowi * NTOK + t + i * 256;
        bf16 h = __float2bfloat16(p);
        P0[idx] = h;
        P1[idx] = __float2bfloat16(p - __bfloat162float(h));
    }
}

// ---------------------------------------------------------------------------
// Host: tensormap encoding via runtime-resolved driver entry point (no -lcuda)
// ---------------------------------------------------------------------------
typedef CUresult (*TMEncodeFn)(
    CUtensorMap*, CUtensorMapDataType, cuuint32_t, void*,
    const cuuint64_t*, const cuuint64_t*, const cuuint32_t*, const cuuint32_t*,
    CUtensorMapInterleave, CUtensorMapSwizzle, CUtensorMapL2promotion,
    CUtensorMapFloatOOBfill);

static TMEncodeFn get_encoder() {
    void* fn = nullptr;
    cudaDriverEntryPointQueryResult st;
    cudaGetDriverEntryPointByVersion("cuTensorMapEncodeTiled", &fn, 12000,
                                     cudaEnableDefault, &st);
    return (TMEncodeFn)fn;
}

// bf16 K-major 2D map: dims {K, R}, box {64, 128}, SW128
static void encode_map(TMEncodeFn enc, CUtensorMap* m, const void* ptr,
                       uint64_t Kdim, uint64_t R) {
    cuuint64_t dims[2]    = {(cuuint64_t)Kdim, (cuuint64_t)R};
    cuuint64_t strides[1] = {(cuuint64_t)(Kdim * 2)};
    cuuint32_t box[2]     = {64u, 128u};
    cuuint32_t es[2]      = {1u, 1u};
    enc(m, CU_TENSOR_MAP_DATA_TYPE_BFLOAT16, 2, (void*)ptr, dims, strides, box, es,
        CU_TENSOR_MAP_INTERLEAVE_NONE, CU_TENSOR_MAP_SWIZZLE_128B,
        CU_TENSOR_MAP_L2_PROMOTION_L2_128B, CU_TENSOR_MAP_FLOAT_OOB_FILL_NONE);
}

extern "C" void kernel_launch(void* const* d_in, const int* in_sizes, int n_in,
                              void* d_out, int out_size)
{
    const float* x   = (const float*)d_in[0];
    const float* Wq  = (const float*)d_in[1];
    const float* Wk  = (const float*)d_in[2];
    const float* Wv  = (const float*)d_in[3];
    const float* bch = (const float*)d_in[4];
    const float* bt  = (const float*)d_in[5];   // step 0 slice
    float* out = (float*)d_out;

    bf16 *x0, *x1, *WtQ0, *WtQ1, *WtK0, *WtK1, *WtV0, *WtV1;
    bf16 *Q0, *Q1, *K0, *K1, *Vt0, *Vt1, *P0, *P1;
    float *S;
    cudaGetSymbolAddress((void**)&x0, g_x0);     cudaGetSymbolAddress((void**)&x1, g_x1);
    cudaGetSymbolAddress((void**)&WtQ0, g_WtQ0); cudaGetSymbolAddress((void**)&WtQ1, g_WtQ1);
    cudaGetSymbolAddress((void**)&WtK0, g_WtK0); cudaGetSymbolAddress((void**)&WtK1, g_WtK1);
    cudaGetSymbolAddress((void**)&WtV0, g_WtV0); cudaGetSymbolAddress((void**)&WtV1, g_WtV1);
    cudaGetSymbolAddress((void**)&Q0, g_Q0);     cudaGetSymbolAddress((void**)&Q1, g_Q1);
    cudaGetSymbolAddress((void**)&K0, g_K0);     cudaGetSymbolAddress((void**)&K1, g_K1);
    cudaGetSymbolAddress((void**)&Vt0, g_Vt0);   cudaGetSymbolAddress((void**)&Vt1, g_Vt1);
    cudaGetSymbolAddress((void**)&S, g_S);
    cudaGetSymbolAddress((void**)&P0, g_P0);     cudaGetSymbolAddress((void**)&P1, g_P1);

    TMEncodeFn enc = get_encoder();

    CUtensorMap mx0, mx1, mWq0, mWq1, mWk0, mWk1, mWv0, mWv1;
    CUtensorMap mQ0, mQ1, mK0, mK1, mV0, mV1, mP0, mP1;
    encode_map(enc, &mx0, x0,   DIN,  NTOK);
    encode_map(enc, &mx1, x1,   DIN,  NTOK);
    encode_map(enc, &mWq0, WtQ0, DIN, DKQ);
    encode_map(enc, &mWq1, WtQ1, DIN, DKQ);
    encode_map(enc, &mWk0, WtK0, DIN, DKQ);
    encode_map(enc, &mWk1, WtK1, DIN, DKQ);
    encode_map(enc, &mWv0, WtV0, DIN, DV);
    encode_map(enc, &mWv1, WtV1, DIN, DV);
    encode_map(enc, &mQ0, Q0,   DKQ,  NTOK);
    encode_map(enc, &mQ1, Q1,   DKQ,  NTOK);
    encode_map(enc, &mK0, K0,   DKQ,  NTOK);
    encode_map(enc, &mK1, K1,   DKQ,  NTOK);
    encode_map(enc, &mV0, Vt0,  NTOK, DV);
    encode_map(enc, &mV1, Vt1,  NTOK, DV);
    encode_map(enc, &mP0, P0,   NTOK, NTOK);
    encode_map(enc, &mP1, P1,   NTOK, NTOK);

    cudaFuncSetAttribute(mma_gemm<1>, cudaFuncAttributeMaxDynamicSharedMemorySize, GEMM_SMEM);
    cudaFuncSetAttribute(mma_gemm<2>, cudaFuncAttributeMaxDynamicSharedMemorySize, GEMM_SMEM);
    cudaFuncSetAttribute(mma_gemm<3>, cudaFuncAttributeMaxDynamicSharedMemorySize, GEMM_SMEM);
    cudaFuncSetAttribute(mma_gemm<4>, cudaFuncAttributeMaxDynamicSharedMemorySize, GEMM_SMEM);

    // Launch order matters for ncu (-s 5 -c 1 captures launch index 5):
    // 0 split, 1 transpose3, 2 gemmQ, 3 gemmK, 4 gemmV, 5 gemmScore <- captured
    split_kernel<<<(NTOK * DIN) / 256, 256>>>(x, x0, x1, NTOK * DIN);

    transpose_split3_kernel<<<dim3(DKQ / 32, DIN / 32, 3), 256>>>(
        Wq, WtQ0, WtQ1, Wk, WtK0, WtK1, Wv, WtV0, WtV1, DIN, DKQ);

    // grids: x = M/128 (cluster pairs along x), y = N/256
    const dim3 gProj(NTOK / 128, DKQ / 256);   // (32, 8)
    mma_gemm<3><<<gProj, 256, GEMM_SMEM>>>(mx0, mx1, mWq0, mWq1,
                                           x0, x1, WtQ0, WtQ1, DKQ, DIN,
                                           nullptr, Q0, Q1, nullptr, nullptr);
    mma_gemm<3><<<gProj, 256, GEMM_SMEM>>>(mx0, mx1, mWk0, mWk1,
                                           x0, x1, WtK0, WtK1, DKQ, DIN,
                                           nullptr, K0, K1, nullptr, nullptr);
    // V = x @ Wv  -> store V^T splits directly (EPI 4)
    mma_gemm<4><<<gProj, 256, GEMM_SMEM>>>(mx0, mx1, mWv0, mWv1,
                                           x0, x1, WtV0, WtV1, DV, DIN,
                                           nullptr, Vt0, Vt1, nullptr, nullptr);

    // scores = (Q @ K^T + channel bias) * rsqrt(dkq)   <- ncu capture target
    const dim3 gScore(NTOK / 128, NTOK / 256);  // (32, 16)
    mma_gemm<1><<<gScore, 256, GEMM_SMEM>>>(mQ0, mQ1, mK0, mK1,
                                            Q0, Q1, K0, K1, NTOK, DKQ,
                                            S, nullptr, nullptr, nullptr, nullptr);

    // softmax -> P splits
    softmax_split_kernel<<<NTOK, 256>>>(S, P0, P1);

    // ctx = P @ V + b_channel + b_t[0] + pe_row(0)
    const dim3 gCtx(NTOK / 128, DV / 256);      // (32, 8)
    mma_gemm<2><<<gCtx, 256, GEMM_SMEM>>>(mP0, mP1, mV0, mV1,
                                          P0, P1, Vt0, Vt1, DV, NTOK,
                                          out, nullptr, nullptr, bch, bt);
}

// round 15
// speedup vs baseline: 1.2376x; 1.1553x over previous
#include <cuda_runtime.h>
#include <cuda.h>
#include <cuda_bf16.h>
#include <cstdint>
#include <cstddef>

using bf16 = __nv_bfloat16;

#define NTOK 4096
#define DIN  2048
#define DKQ  2048
#define DV   2048

#if defined(__CUDA_ARCH_FEAT_SM103_ALL) || defined(__CUDA_ARCH_FEAT_SM100_ALL)
#define HAS_TCGEN05 1
#else
#define HAS_TCGEN05 0
#endif

__device__ __forceinline__ uint32_t smem_u32(const void* p) {
    uint32_t a;
    asm("{ .reg .u64 t; cvta.to.shared.u64 t, %1; cvt.u32.u64 %0, t; }" : "=r"(a) : "l"(p));
    return a;
}

#if HAS_TCGEN05
__device__ __forceinline__ uint32_t elect_one_pred() {
    uint32_t pred;
    asm volatile("{\n\t.reg .pred p;\n\telect.sync _|p, 0xFFFFFFFF;\n\tselp.b32 %0, 1, 0, p;\n\t}" : "=r"(pred));
    return pred;
}
__device__ __forceinline__ uint32_t cluster_rank() {
    uint32_t r;
    asm("mov.u32 %0, %%cluster_ctarank;" : "=r"(r));
    return r;
}
#define TCGEN05_ALLOC_CG2(sa, n) \
    asm volatile("tcgen05.alloc.cta_group::2.sync.aligned.shared::cta.b32 [%0], %1;" \
        :: "r"((uint32_t)(sa)), "r"((uint32_t)(n)) : "memory")
#define TCGEN05_DEALLOC_CG2(t, n) \
    asm volatile("tcgen05.dealloc.cta_group::2.sync.aligned.b32 %0, %1;" :: "r"(t), "r"((uint32_t)(n)))
#define TCGEN05_RELINQ_CG2() \
    asm volatile("tcgen05.relinquish_alloc_permit.cta_group::2.sync.aligned;")
#define TCGEN05_COMMIT_MCAST_CG2(mb, mask) \
    asm volatile("tcgen05.commit.cta_group::2.mbarrier::arrive::one.shared::cluster.multicast::cluster.b64 [%0], %1;" \
        :: "r"((uint32_t)(mb)), "h"((uint16_t)(mask)) : "memory")
#define TCGEN05_WAIT_LD() asm volatile("tcgen05.wait::ld.sync.aligned;" ::: "memory")
#define TCGEN05_FENCE_AFTER() asm volatile("tcgen05.fence::after_thread_sync;" ::: "memory")
#define TCGEN05_FENCE_BEFORE() asm volatile("tcgen05.fence::before_thread_sync;" ::: "memory")
#define MBARRIER_INIT(mb, c) \
    asm volatile("mbarrier.init.shared.b64 [%0], %1;" :: "r"((uint32_t)(mb)), "r"((uint32_t)(c)) : "memory")
#define MBARRIER_INVAL(mb) \
    asm volatile("mbarrier.inval.shared.b64 [%0];" :: "r"((uint32_t)(mb)) : "memory")
#define MBARRIER_EXPECT_TX(mb, b) \
    asm volatile("mbarrier.arrive.expect_tx.shared.b64 _, [%0], %1;" \
        :: "r"((uint32_t)(mb)), "r"((uint32_t)(b)) : "memory")
#define MBARRIER_ARRIVE_REMOTE(mb, trank) \
    asm volatile("{\n\t.reg .b32 ra;\n\t" \
        "mapa.shared::cluster.u32 ra, %0, %1;\n\t" \
        "mbarrier.arrive.shared::cluster.b64 _, [ra];\n\t}" \
        :: "r"((uint32_t)(mb)), "r"((uint32_t)(trank)) : "memory")
#define MBARRIER_WAIT_PARITY(mb, par) do { \
    uint32_t _mb = (uint32_t)(mb); uint32_t _p = (uint32_t)(par); uint32_t _d; \
    asm volatile("{\n\t.reg .pred p;\n\t" \
        "mbarrier.try_wait.parity.acquire.cta.shared::cta.b64 p, [%1], %2;\n\t" \
        "selp.b32 %0, 1, 0, p;\n\t}" : "=r"(_d) : "r"(_mb), "r"(_p) : "memory"); \
    if (!_d) { \
        asm volatile("{\n\t.reg .pred P1;\n\t" \
            "WAIT_LOOP_%=:\n\t" \
            "mbarrier.try_wait.parity.acquire.cta.shared::cta.b64 P1, [%0], %1, 0x989680;\n\t" \
            "@P1 bra.uni WAIT_DONE_%=;\n\t" \
            "bra.uni WAIT_LOOP_%=;\n\t" \
            "WAIT_DONE_%=:\n\t}" :: "r"(_mb), "r"(_p) : "memory"); \
    } } while (0)
#define CLUSTER_ARRIVE() asm volatile("barrier.cluster.arrive.aligned;" ::: "memory")
#define CLUSTER_WAIT()   asm volatile("barrier.cluster.wait.aligned;" ::: "memory")
#define TCGEN05_LD_32X32B_X32(r, ta) \
    asm volatile("tcgen05.ld.sync.aligned.32x32b.x32.b32 " \
        "{%0, %1, %2, %3, %4, %5, %6, %7, %8, %9, %10, %11, %12, %13, %14, %15, " \
        " %16, %17, %18, %19, %20, %21, %22, %23, %24, %25, %26, %27, %28, %29, %30, %31}, [%32];" \
        : "=r"((r)[0]),  "=r"((r)[1]),  "=r"((r)[2]),  "=r"((r)[3]), \
          "=r"((r)[4]),  "=r"((r)[5]),  "=r"((r)[6]),  "=r"((r)[7]), \
          "=r"((r)[8]),  "=r"((r)[9]),  "=r"((r)[10]), "=r"((r)[11]), \
          "=r"((r)[12]), "=r"((r)[13]), "=r"((r)[14]), "=r"((r)[15]), \
          "=r"((r)[16]), "=r"((r)[17]), "=r"((r)[18]), "=r"((r)[19]), \
          "=r"((r)[20]), "=r"((r)[21]), "=r"((r)[22]), "=r"((r)[23]), \
          "=r"((r)[24]), "=r"((r)[25]), "=r"((r)[26]), "=r"((r)[27]), \
          "=r"((r)[28]), "=r"((r)[29]), "=r"((r)[30]), "=r"((r)[31]) \
        : "r"(ta))

// cg2 TMA 2D: both CTAs execute; data lands in the issuing CTA's SMEM but
// complete_tx targets the LEADER CTA's barrier (bit 24 = peer bit, cleared).
__device__ __forceinline__ void tma_load_2d_cg2(uint32_t smem_addr, const void* map,
                                                int cx, int cy, uint32_t mbar) {
    asm volatile(
        "{\n\t.reg .b32 lb;\n\t"
        "and.b32 lb, %4, 0xFEFFFFFF;\n\t"
        "cp.async.bulk.tensor.2d.cta_group::2.shared::cluster.global.tile"
        ".mbarrier::complete_tx::bytes [%0], [%1, {%2, %3}], [lb];\n\t"
        "}"
        :: "r"(smem_addr), "l"(map), "r"(cx), "r"(cy), "r"(mbar) : "memory");
}

// K-major SW128 smem descriptor (LBO=1, SBO=64, version=1, layout=SW128)
static constexpr uint64_t SMEM_DESC_BASE_SW128 =
    (uint64_t(2) << 61) | (uint64_t(1) << 46) | (uint64_t(64) << 32) | (uint64_t(1) << 16);
#define MAKE_SMEM_DESC(a) (SMEM_DESC_BASE_SW128 | ((uint64_t)((a) >> 4) & 0x3FFF))

// kind::f16 cg2 mma: bf16 in, fp32 acc, M=256 (pair), N=256, K-major both
static constexpr uint32_t MMA_IDESC_M256N256 =
    (1u << 4) | (1u << 7) | (1u << 10) | ((256u / 8u) << 17) | ((256u / 16u) << 24);

__device__ __forceinline__ void mma_f16_ss_cg2(uint32_t d, uint64_t a, uint64_t b, bool en) {
    uint32_t e = en ? 1u : 0u;
    asm volatile(
        "{\n\t.reg .pred p;\n\t"
        "setp.ne.u32 p, %5, 0;\n\t"
        "tcgen05.mma.cta_group::2.kind::f16 [%0], %1, %2, %3, "
        "{%4, %4, %4, %4, %4, %4, %4, %4}, p;\n\t"
        "}"
        :: "r"(d), "l"(a), "l"(b), "r"(MMA_IDESC_M256N256), "r"(0u), "r"(e)
        : "memory");
}
#endif  // HAS_TCGEN05

// ---------------------------------------------------------------------------
// Scratch (device globals; allocation-free rule)
// ---------------------------------------------------------------------------
__device__ bf16  g_x0[(size_t)NTOK * DIN],  g_x1[(size_t)NTOK * DIN];
__device__ bf16  g_WtQ0[(size_t)DKQ * DIN], g_WtQ1[(size_t)DKQ * DIN];
__device__ bf16  g_WtK0[(size_t)DKQ * DIN], g_WtK1[(size_t)DKQ * DIN];
__device__ bf16  g_WtV0[(size_t)DV * DIN],  g_WtV1[(size_t)DV * DIN];
__device__ bf16  g_Q0[(size_t)NTOK * DKQ],  g_Q1[(size_t)NTOK * DKQ];
__device__ bf16  g_K0[(size_t)NTOK * DKQ],  g_K1[(size_t)NTOK * DKQ];
__device__ bf16  g_Vt0[(size_t)DV * NTOK],  g_Vt1[(size_t)DV * NTOK];
__device__ float g_S [(size_t)NTOK * NTOK];
__device__ bf16  g_P0[(size_t)NTOK * NTOK], g_P1[(size_t)NTOK * NTOK];

// ---------------------------------------------------------------------------
// PERSISTENT cg2 tcgen05 GEMM with TMEM double-buffering.
// Grid = 148 CTAs (74 cg2 pairs), cluster (2,1,1). Each pair loops over its
// round-robin tile list (M-major; M tiles = NTOK/256 = 16 always). Per tile:
// 256x256 output, TMEM buffer = (localTile & 1) * 256 cols (512-col alloc).
// Consumer starts tile t+1's MMAs while epilogue warps (0-3, both CTAs) drain
// tile t's buffer -> epilogue hidden under MMA.
// Stage ring: 3 x 64KB, continuous across tiles. Producer warp 7 (both CTAs;
// cg2-TMA tx -> leader full barrier). Consumer warp 6 (leader only).
// done[buf]: cg2 mcast commit -> both CTAs. epi_free[buf]: count 2 on leader,
// both CTAs' epilogues arrive remotely; consumer gates buffer reuse.
// EPI 1: (+channel bias)*rsqrt(dkq) fp32.  EPI 2: +e0+e1+(c&1) fp32.
// EPI 3: bf16x2 split store (row-major).   EPI 4: bf16x2 split store TRANSPOSED.
// ---------------------------------------------------------------------------
#define OFF_A0 0
#define OFF_A1 (16 * 1024)
#define OFF_B0 (32 * 1024)
#define OFF_B1 (48 * 1024)
#define STAGE_BYTES (64 * 1024)
#define NSTAGE 3
#define OFF_SCRATCH 1024
#define OFF_STAGE0  18432                              // 1024-aligned, after scratch
#define GEMM_SMEM  (OFF_STAGE0 + NSTAGE * STAGE_BYTES) // 215040

#define MB_FULL(s)    (16 + (s) * 8)
#define MB_EMPTY(s)   (40 + (s) * 8)
#define MB_DONE(b)    (64 + (b) * 8)
#define MB_EPIFREE(b) (80 + (b) * 8)

#define MTILES 16   // NTOK / 256, A rows are always NTOK

template<int EPI>
__global__ __launch_bounds__(256, 1) __cluster_dims__(2, 1, 1)
void mma_gemm(const __grid_constant__ CUtensorMap ma0,
              const __grid_constant__ CUtensorMap ma1,
              const __grid_constant__ CUtensorMap mb0,
              const __grid_constant__ CUtensorMap mb1,
              const bf16* __restrict__ A0, const bf16* __restrict__ A1,
              const bf16* __restrict__ B0, const bf16* __restrict__ B1,
              int N, int K,
              float* __restrict__ Cf, bf16* __restrict__ C0, bf16* __restrict__ C1,
              const float* __restrict__ e0, const float* __restrict__ e1)
{
#if HAS_TCGEN05
    extern __shared__ char smem[];
    const uint32_t sb = smem_u32(smem);
    const int tid = threadIdx.x;
    const int wid = tid >> 5;
    const int lid = tid & 31;
    const uint32_t rank = cluster_rank();     // 0 = leader of the MMA pair
    const int pairCnt = gridDim.x >> 1;
    const int pairIdx = blockIdx.x >> 1;
    const int Ntiles = N >> 8;
    const int totalTiles = MTILES * Ntiles;
    const int NC = K >> 6;

    if (wid == 0) {
        TCGEN05_ALLOC_CG2(sb + 0, 512);       // two 256-col accumulator buffers
        TCGEN05_RELINQ_CG2();
    }
    if (tid == 0) {
#pragma unroll
        for (int s = 0; s < NSTAGE; s++) {
            MBARRIER_INIT(sb + MB_FULL(s), 1);
            MBARRIER_INIT(sb + MB_EMPTY(s), 1);
        }
        MBARRIER_INIT(sb + MB_DONE(0), 1);
        MBARRIER_INIT(sb + MB_DONE(1), 1);
        MBARRIER_INIT(sb + MB_EPIFREE(0), 2);  // arrivals from BOTH CTAs' epilogues
        MBARRIER_INIT(sb + MB_EPIFREE(1), 2);
    }
    __syncthreads();
    CLUSTER_ARRIVE();
    CLUSTER_WAIT();

    uint32_t tmem;
    asm volatile("ld.shared.b32 %0, [%1];" : "=r"(tmem) : "r"(sb + 0));

    if (wid == 7) {
        // -------- TMA producer (both CTAs; tx -> leader full barrier) --------
        if (elect_one_pred()) {
            int pe[NSTAGE] = {0, 0, 0};
            int gch = 0;
            for (int t = pairIdx; t < totalTiles; t += pairCnt) {
                const int mt = t & (MTILES - 1);
                const int nt = t / MTILES;
                const int bmT = mt * 256 + (int)rank * 128;
                const int bnT = nt * 256 + (int)rank * 128;
                for (int ch = 0; ch < NC; ch++, gch++) {
                    const int s = gch % NSTAGE;
                    const uint32_t stg = sb + OFF_STAGE0 + s * STAGE_BYTES;
                    if (gch >= NSTAGE) { MBARRIER_WAIT_PARITY(sb + MB_EMPTY(s), pe[s]); pe[s] ^= 1; }
                    const uint32_t fullb = sb + MB_FULL(s);
                    if (rank == 0) MBARRIER_EXPECT_TX(fullb, 2 * STAGE_BYTES);
                    const int kx = ch * 64;
                    tma_load_2d_cg2(stg + OFF_A0, &ma0, kx, bmT, fullb);
                    tma_load_2d_cg2(stg + OFF_A1, &ma1, kx, bmT, fullb);
                    tma_load_2d_cg2(stg + OFF_B0, &mb0, kx, bnT, fullb);
                    tma_load_2d_cg2(stg + OFF_B1, &mb1, kx, bnT, fullb);
                }
            }
        }
    } else if (wid == 6 && rank == 0) {
        // ---------------- leader MMA consumer ----------------
        if (elect_one_pred()) {
            int pf[NSTAGE] = {0, 0, 0};
            int pef[2] = {0, 0};
            int gch = 0, ti = 0;
            for (int t = pairIdx; t < totalTiles; t += pairCnt, ti++) {
                const int buf = ti & 1;
                if (ti >= 2) { MBARRIER_WAIT_PARITY(sb + MB_EPIFREE(buf), pef[buf]); pef[buf] ^= 1; }
                const uint32_t dst = tmem + buf * 256;
                for (int ch = 0; ch < NC; ch++, gch++) {
                    const int s = gch % NSTAGE;
                    const uint32_t stg = sb + OFF_STAGE0 + s * STAGE_BYTES;
                    MBARRIER_WAIT_PARITY(sb + MB_FULL(s), pf[s]); pf[s] ^= 1;
                    const uint64_t dA0 = MAKE_SMEM_DESC(stg + OFF_A0);
                    const uint64_t dA1 = MAKE_SMEM_DESC(stg + OFF_A1);
                    const uint64_t dB0 = MAKE_SMEM_DESC(stg + OFF_B0);
                    const uint64_t dB1 = MAKE_SMEM_DESC(stg + OFF_B1);
#pragma unroll
                    for (int ks = 0; ks < 4; ks++) {
                        const uint64_t o = (uint64_t)(ks * 2);   // +32B per K=16 step
                        mma_f16_ss_cg2(dst, dA0 + o, dB0 + o, (ch > 0) || (ks > 0));
                        mma_f16_ss_cg2(dst, dA0 + o, dB1 + o, true);
                        mma_f16_ss_cg2(dst, dA1 + o, dB0 + o, true);
                    }
                    TCGEN05_COMMIT_MCAST_CG2(sb + MB_EMPTY(s), 3);
                }
                TCGEN05_COMMIT_MCAST_CG2(sb + MB_DONE(buf), 3);
            }
        }
    }

    // -------- epilogue: warps 0-3, both CTAs, overlapped with next tile -----
    if (tid < 128) {
        float* tp = ((float*)(smem + OFF_SCRATCH)) + wid * (33 * 32);
        int pd[2] = {0, 0};
        int ti = 0;
        for (int t = pairIdx; t < totalTiles; t += pairCnt, ti++) {
            const int buf = ti & 1;
            MBARRIER_WAIT_PARITY(sb + MB_DONE(buf), pd[buf]); pd[buf] ^= 1;
            TCGEN05_FENCE_AFTER();
            const int mt = t & (MTILES - 1);
            const int nt = t / MTILES;
            const int r0 = mt * 256 + (int)rank * 128 + wid * 32;
            const int bn = nt * 256;
            const uint32_t tbase = tmem + buf * 256;
#pragma unroll 1
            for (int cb = 0; cb < 8; cb++) {
                uint32_t d[32];
                TCGEN05_LD_32X32B_X32(d, tbase + cb * 32);
                TCGEN05_WAIT_LD();
                const int cbase = bn + cb * 32;
                if (EPI == 4) {
                    const int r = r0 + lid;
#pragma unroll
                    for (int j = 0; j < 32; j++) {
                        float v = __uint_as_float(d[j]);
                        bf16 h = __float2bfloat16(v);
                        const size_t idx = (size_t)(cbase + j) * NTOK + r;
                        C0[idx] = h;
                        C1[idx] = __float2bfloat16(v - __bfloat162float(h));
                    }
                } else {
#pragma unroll
                    for (int j = 0; j < 32; j++) tp[lid * 33 + j] = __uint_as_float(d[j]);
                    __syncwarp();
                    const int c = cbase + lid;
#pragma unroll 1
                    for (int i = 0; i < 32; i++) {
                        const int r = r0 + i;
                        const float v = tp[i * 33 + lid];
                        const size_t idx = (size_t)r * N + c;
                        if (EPI == 1) {
                            Cf[idx] = (v + (((r >> 6) == (c >> 6)) ? 1.0f : 0.0f))
                                      * 0.022097086912079608f;   // 1/sqrt(2048)
                        } else if (EPI == 2) {
                            Cf[idx] = v + e0[idx] + e1[idx] + (float)(c & 1);
                        } else {  // EPI == 3
                            bf16 h = __float2bfloat16(v);
                            C0[idx] = h;
                            C1[idx] = __float2bfloat16(v - __bfloat162float(h));
                        }
                    }
                    __syncwarp();
                }
            }
            TCGEN05_FENCE_BEFORE();
            asm volatile("bar.sync 1, 128;" ::: "memory");   // all 4 epi warps done
            if (tid == 0) MBARRIER_ARRIVE_REMOTE(sb + MB_EPIFREE(buf), 0);
        }
    }

    __syncthreads();
    CLUSTER_ARRIVE();
    CLUSTER_WAIT();
    if (tid == 0) {
#pragma unroll
        for (int s = 0; s < NSTAGE; s++) {
            MBARRIER_INVAL(sb + MB_FULL(s));
            MBARRIER_INVAL(sb + MB_EMPTY(s));
        }
        MBARRIER_INVAL(sb + MB_DONE(0));  MBARRIER_INVAL(sb + MB_DONE(1));
        MBARRIER_INVAL(sb + MB_EPIFREE(0)); MBARRIER_INVAL(sb + MB_EPIFREE(1));
    }
    __syncthreads();
    if (wid == 0) TCGEN05_DEALLOC_CG2(tmem, 512);
    CLUSTER_ARRIVE();
    CLUSTER_WAIT();
#else
    // ============ FFMA fallback (base sm_103): persistent tile loop =========
    extern __shared__ char smemraw[];
    float* Asf = (float*)smemraw;            // [2][8][128]
    float* Bsf = Asf + 2 * 8 * 128;          // [2][8][128]

    const int t0  = threadIdx.x;
    const int rank = blockIdx.x & 1;
    const int pairCnt = gridDim.x >> 1;
    const int pairIdx = blockIdx.x >> 1;
    const int Ntiles = N >> 8;
    const int totalTiles = MTILES * Ntiles;
    const int arow = t0 >> 1;
    const int acol = (t0 & 1) << 2;
    const int tx = t0 & 15;
    const int ty = t0 >> 4;

    for (int t = pairIdx; t < totalTiles; t += pairCnt) {
        const int mt = t & (MTILES - 1);
        const int nt = t / MTILES;
        const int bm = mt * 256 + rank * 128;
        for (int half = 0; half < 2; half++) {
            const int bn = nt * 256 + half * 128;
            const bf16* A0p = A0 + (size_t)(bm + arow) * K + acol;
            const bf16* A1p = A1 + (size_t)(bm + arow) * K + acol;
            const bf16* B0p = B0 + (size_t)(bn + arow) * K + acol;
            const bf16* B1p = B1 + (size_t)(bn + arow) * K + acol;

            float acc[8][8];
#pragma unroll
            for (int i = 0; i < 8; i++)
#pragma unroll
                for (int j = 0; j < 8; j++) acc[i][j] = 0.0f;

            {
                const __nv_bfloat162* qa0 = (const __nv_bfloat162*)A0p;
                const __nv_bfloat162* qa1 = (const __nv_bfloat162*)A1p;
                const __nv_bfloat162* qb0 = (const __nv_bfloat162*)B0p;
                const __nv_bfloat162* qb1 = (const __nv_bfloat162*)B1p;
                float2 a0 = __bfloat1622float2(qa0[0]), a1 = __bfloat1622float2(qa0[1]);
                float2 c0 = __bfloat1622float2(qa1[0]), c1 = __bfloat1622float2(qa1[1]);
                float2 b0 = __bfloat1622float2(qb0[0]), b1 = __bfloat1622float2(qb0[1]);
                float2 d0 = __bfloat1622float2(qb1[0]), d1 = __bfloat1622float2(qb1[1]);
                Asf[(acol + 0) * 128 + arow] = a0.x + c0.x;
                Asf[(acol + 1) * 128 + arow] = a0.y + c0.y;
                Asf[(acol + 2) * 128 + arow] = a1.x + c1.x;
                Asf[(acol + 3) * 128 + arow] = a1.y + c1.y;
                Bsf[(acol + 0) * 128 + arow] = b0.x + d0.x;
                Bsf[(acol + 1) * 128 + arow] = b0.y + d0.y;
                Bsf[(acol + 2) * 128 + arow] = b1.x + d1.x;
                Bsf[(acol + 3) * 128 + arow] = b1.y + d1.y;
            }
            __syncthreads();

            const int KT = K >> 3;
            int buf = 0;
            for (int kt = 0; kt < KT; kt++) {
                float4 aN = make_float4(0, 0, 0, 0), bN = make_float4(0, 0, 0, 0);
                const bool has = (kt + 1 < KT);
                if (has) {
                    const size_t o = (size_t)(kt + 1) * 8;
                    const __nv_bfloat162* qa0 = (const __nv_bfloat162*)(A0p + o);
                    const __nv_bfloat162* qa1 = (const __nv_bfloat162*)(A1p + o);
                    const __nv_bfloat162* qb0 = (const __nv_bfloat162*)(B0p + o);
                    const __nv_bfloat162* qb1 = (const __nv_bfloat162*)(B1p + o);
                    float2 a0 = __bfloat1622float2(qa0[0]), a1 = __bfloat1622float2(qa0[1]);
                    float2 c0 = __bfloat1622float2(qa1[0]), c1 = __bfloat1622float2(qa1[1]);
                    float2 b0 = __bfloat1622float2(qb0[0]), b1 = __bfloat1622float2(qb0[1]);
                    float2 d0 = __bfloat1622float2(qb1[0]), d1 = __bfloat1622float2(qb1[1]);
                    aN = make_float4(a0.x + c0.x, a0.y + c0.y, a1.x + c1.x, a1.y + c1.y);
                    bN = make_float4(b0.x + d0.x, b0.y + d0.y, b1.x + d1.x, b1.y + d1.y);
                }
                const float* Ab = Asf + buf * 1024;
                const float* Bb = Bsf + buf * 1024;
#pragma unroll
                for (int k = 0; k < 8; k++) {
                    float4 a0 = *(const float4*)&Ab[k * 128 + ty * 4];
                    float4 a1 = *(const float4*)&Ab[k * 128 + 64 + ty * 4];
                    float4 b0 = *(const float4*)&Bb[k * 128 + tx * 4];
                    float4 b1 = *(const float4*)&Bb[k * 128 + 64 + tx * 4];
                    float av[8] = {a0.x, a0.y, a0.z, a0.w, a1.x, a1.y, a1.z, a1.w};
                    float bv[8] = {b0.x, b0.y, b0.z, b0.w, b1.x, b1.y, b1.z, b1.w};
#pragma unroll
                    for (int i = 0; i < 8; i++)
#pragma unroll
                        for (int j = 0; j < 8; j++)
                            acc[i][j] = fmaf(av[i], bv[j], acc[i][j]);
                }
                if (has) {
                    const int nb = buf ^ 1;
                    float* An = Asf + nb * 1024;
                    float* Bn = Bsf + nb * 1024;
                    An[(acol + 0) * 128 + arow] = aN.x; An[(acol + 1) * 128 + arow] = aN.y;
                    An[(acol + 2) * 128 + arow] = aN.z; An[(acol + 3) * 128 + arow] = aN.w;
                    Bn[(acol + 0) * 128 + arow] = bN.x; Bn[(acol + 1) * 128 + arow] = bN.y;
                    Bn[(acol + 2) * 128 + arow] = bN.z; Bn[(acol + 3) * 128 + arow] = bN.w;
                }
                __syncthreads();
                buf ^= 1;
            }

#pragma unroll
            for (int i = 0; i < 8; i++) {
                const int r = bm + ((i < 4) ? (ty * 4 + i) : (64 + ty * 4 + (i - 4)));
#pragma unroll
                for (int j = 0; j < 8; j++) {
                    const int c = bn + ((j < 4) ? (tx * 4 + j) : (64 + tx * 4 + (j - 4)));
                    float v = acc[i][j];
                    if (EPI == 1) {
                        Cf[(size_t)r * N + c] =
                            (v + (((r >> 6) == (c >> 6)) ? 1.0f : 0.0f)) * 0.022097086912079608f;
                    } else if (EPI == 2) {
                        const size_t idx = (size_t)r * N + c;
                        Cf[idx] = v + e0[idx] + e1[idx] + (float)(c & 1);
                    } else if (EPI == 3) {
                        const size_t idx = (size_t)r * N + c;
                        bf16 h = __float2bfloat16(v);
                        C0[idx] = h;
                        C1[idx] = __float2bfloat16(v - __bfloat162float(h));
                    } else {  // EPI == 4: transposed split
                        const size_t idx = (size_t)c * NTOK + r;
                        bf16 h = __float2bfloat16(v);
                        C0[idx] = h;
                        C1[idx] = __float2bfloat16(v - __bfloat162float(h));
                    }
                }
            }
            __syncthreads();
        }
    }
#endif
}

// ---------------------------------------------------------------------------
// bf16x2 split; fused 3-way transpose-split (z selects tensor)
// ---------------------------------------------------------------------------
__global__ __launch_bounds__(256)
void split_kernel(const float* __restrict__ in, bf16* __restrict__ o0,
                  bf16* __restrict__ o1, int n)
{
    int i = blockIdx.x * 256 + threadIdx.x;
    if (i < n) {
        float v = in[i];
        bf16 h = __float2bfloat16(v);
        o0[i] = h;
        o1[i] = __float2bfloat16(v - __bfloat162float(h));
    }
}

__global__ __launch_bounds__(256)
void transpose_split3_kernel(const float* __restrict__ sA, bf16* __restrict__ a0, bf16* __restrict__ a1,
                             const float* __restrict__ sB, bf16* __restrict__ b0, bf16* __restrict__ b1,
                             const float* __restrict__ sC, bf16* __restrict__ c0, bf16* __restrict__ c1,
                             int R, int C)
{
    __shared__ float tile[32][33];
    const float* in = (blockIdx.z == 0) ? sA : (blockIdx.z == 1) ? sB : sC;
    bf16* o0 = (blockIdx.z == 0) ? a0 : (blockIdx.z == 1) ? b0 : c0;
    bf16* o1 = (blockIdx.z == 0) ? a1 : (blockIdx.z == 1) ? b1 : c1;
    const int c0i = blockIdx.x * 32;
    const int r0i = blockIdx.y * 32;
    const int tx = threadIdx.x & 31;
    const int ty = threadIdx.x >> 5;
#pragma unroll
    for (int i = 0; i < 32; i += 8)
        tile[ty + i][tx] = in[(size_t)(r0i + ty + i) * C + c0i + tx];
    __syncthreads();
#pragma unroll
    for (int i = 0; i < 32; i += 8) {
        float v = tile[tx][ty + i];
        const size_t idx = (size_t)(c0i + ty + i) * R + r0i + tx;
        bf16 h = __float2bfloat16(v);
        o0[idx] = h;
        o1[idx] = __float2bfloat16(v - __bfloat162float(h));
    }
}

// ---------------------------------------------------------------------------
// Row softmax over S[4096,4096] -> bf16x2 split P
// ---------------------------------------------------------------------------
__device__ __forceinline__ float warpMax(float v) {
#pragma unroll
    for (int o = 16; o > 0; o >>= 1) v = fmaxf(v, __shfl_xor_sync(0xffffffffu, v, o));
    return v;
}
__device__ __forceinline__ float warpSum(float v) {
#pragma unroll
    for (int o = 16; o > 0; o >>= 1) v += __shfl_xor_sync(0xffffffffu, v, o);
    return v;
}

__global__ __launch_bounds__(256)
void softmax_split_kernel(const float* __restrict__ S, bf16* __restrict__ P0,
                          bf16* __restrict__ P1)
{
    __shared__ float red[8];
    __shared__ float bcast;
    const int rowi = blockIdx.x;
    const int t = threadIdx.x;
    const float* __restrict__ Sr = S + (size_t)rowi * NTOK;

    float v[16];
    float m = -3.402823466e38f;
#pragma unroll
    for (int i = 0; i < 16; i++) {
        v[i] = Sr[t + i * 256];
        m = fmaxf(m, v[i]);
    }
    m = warpMax(m);
    if ((t & 31) == 0) red[t >> 5] = m;
    __syncthreads();
    if (t < 32) {
        float x = (t < 8) ? red[t] : -3.402823466e38f;
        x = warpMax(x);
        if (t == 0) bcast = x;
    }
    __syncthreads();
    m = bcast;

    float s = 0.0f;
#pragma unroll
    for (int i = 0; i < 16; i++) {
        v[i] = expf(v[i] - m);
        s += v[i];
    }
    s = warpSum(s);
    if ((t & 31) == 0) red[t >> 5] = s;
    __syncthreads();
    if (t < 32) {
        float x = (t < 8) ? red[t] : 0.0f;
        x = warpSum(x);
        if (t == 0) bcast = x;
    }
    __syncthreads();
    const float inv = 1.0f / bcast;
#pragma unroll
    for (int i = 0; i < 16; i++) {
        const float p = v[i] * inv;
        const size_t idx = (size_t)rowi * NTOK + t + i * 256;
        bf16 h = __float2bfloat16(p);
        P0[idx] = h;
        P1[idx] = __float2bfloat16(p - __bfloat162float(h));
    }
}

// ---------------------------------------------------------------------------
// Host: tensormap encoding via runtime-resolved driver entry point (no -lcuda)
// ---------------------------------------------------------------------------
typedef CUresult (*TMEncodeFn)(
    CUtensorMap*, CUtensorMapDataType, cuuint32_t, void*,
    const cuuint64_t*, const cuuint64_t*, const cuuint32_t*, const cuuint32_t*,
    CUtensorMapInterleave, CUtensorMapSwizzle, CUtensorMapL2promotion,
    CUtensorMapFloatOOBfill);

static TMEncodeFn get_encoder() {
    void* fn = nullptr;
    cudaDriverEntryPointQueryResult st;
    cudaGetDriverEntryPointByVersion("cuTensorMapEncodeTiled", &fn, 12000,
                                     cudaEnableDefault, &st);
    return (TMEncodeFn)fn;
}

// bf16 K-major 2D map: dims {K, R}, box {64, 128}, SW128
static void encode_map(TMEncodeFn enc, CUtensorMap* m, const void* ptr,
                       uint64_t Kdim, uint64_t R) {
    cuuint64_t dims[2]    = {(cuuint64_t)Kdim, (cuuint64_t)R};
    cuuint64_t strides[1] = {(cuuint64_t)(Kdim * 2)};
    cuuint32_t box[2]     = {64u, 128u};
    cuuint32_t es[2]      = {1u, 1u};
    enc(m, CU_TENSOR_MAP_DATA_TYPE_BFLOAT16, 2, (void*)ptr, dims, strides, box, es,
        CU_TENSOR_MAP_INTERLEAVE_NONE, CU_TENSOR_MAP_SWIZZLE_128B,
        CU_TENSOR_MAP_L2_PROMOTION_L2_128B, CU_TENSOR_MAP_FLOAT_OOB_FILL_NONE);
}

extern "C" void kernel_launch(void* const* d_in, const int* in_sizes, int n_in,
                              void* d_out, int out_size)
{
    const float* x   = (const float*)d_in[0];
    const float* Wq  = (const float*)d_in[1];
    const float* Wk  = (const float*)d_in[2];
    const float* Wv  = (const float*)d_in[3];
    const float* bch = (const float*)d_in[4];
    const float* bt  = (const float*)d_in[5];   // step 0 slice
    float* out = (float*)d_out;

    bf16 *x0, *x1, *WtQ0, *WtQ1, *WtK0, *WtK1, *WtV0, *WtV1;
    bf16 *Q0, *Q1, *K0, *K1, *Vt0, *Vt1, *P0, *P1;
    float *S;
    cudaGetSymbolAddress((void**)&x0, g_x0);     cudaGetSymbolAddress((void**)&x1, g_x1);
    cudaGetSymbolAddress((void**)&WtQ0, g_WtQ0); cudaGetSymbolAddress((void**)&WtQ1, g_WtQ1);
    cudaGetSymbolAddress((void**)&WtK0, g_WtK0); cudaGetSymbolAddress((void**)&WtK1, g_WtK1);
    cudaGetSymbolAddress((void**)&WtV0, g_WtV0); cudaGetSymbolAddress((void**)&WtV1, g_WtV1);
    cudaGetSymbolAddress((void**)&Q0, g_Q0);     cudaGetSymbolAddress((void**)&Q1, g_Q1);
    cudaGetSymbolAddress((void**)&K0, g_K0);     cudaGetSymbolAddress((void**)&K1, g_K1);
    cudaGetSymbolAddress((void**)&Vt0, g_Vt0);   cudaGetSymbolAddress((void**)&Vt1, g_Vt1);
    cudaGetSymbolAddress((void**)&S, g_S);
    cudaGetSymbolAddress((void**)&P0, g_P0);     cudaGetSymbolAddress((void**)&P1, g_P1);

    TMEncodeFn enc = get_encoder();

    CUtensorMap mx0, mx1, mWq0, mWq1, mWk0, mWk1, mWv0, mWv1;
    CUtensorMap mQ0, mQ1, mK0, mK1, mV0, mV1, mP0, mP1;
    encode_map(enc, &mx0, x0,   DIN,  NTOK);
    encode_map(enc, &mx1, x1,   DIN,  NTOK);
    encode_map(enc, &mWq0, WtQ0, DIN, DKQ);
    encode_map(enc, &mWq1, WtQ1, DIN, DKQ);
    encode_map(enc, &mWk0, WtK0, DIN, DKQ);
    encode_map(enc, &mWk1, WtK1, DIN, DKQ);
    encode_map(enc, &mWv0, WtV0, DIN, DV);
    encode_map(enc, &mWv1, WtV1, DIN, DV);
    encode_map(enc, &mQ0, Q0,   DKQ,  NTOK);
    encode_map(enc, &mQ1, Q1,   DKQ,  NTOK);
    encode_map(enc, &mK0, K0,   DKQ,  NTOK);
    encode_map(enc, &mK1, K1,   DKQ,  NTOK);
    encode_map(enc, &mV0, Vt0,  NTOK, DV);
    encode_map(enc, &mV1, Vt1,  NTOK, DV);
    encode_map(enc, &mP0, P0,   NTOK, NTOK);
    encode_map(enc, &mP1, P1,   NTOK, NTOK);

    cudaFuncSetAttribute(mma_gemm<1>, cudaFuncAttributeMaxDynamicSharedMemorySize, GEMM_SMEM);
    cudaFuncSetAttribute(mma_gemm<2>, cudaFuncAttributeMaxDynamicSharedMemorySize, GEMM_SMEM);
    cudaFuncSetAttribute(mma_gemm<3>, cudaFuncAttributeMaxDynamicSharedMemorySize, GEMM_SMEM);
    cudaFuncSetAttribute(mma_gemm<4>, cudaFuncAttributeMaxDynamicSharedMemorySize, GEMM_SMEM);

    // Launch order matters for ncu (-s 5 -c 1 captures launch index 5):
    // 0 split, 1 transpose3, 2 gemmQ, 3 gemmK, 4 gemmV, 5 gemmScore <- captured
    split_kernel<<<(NTOK * DIN) / 256, 256>>>(x, x0, x1, NTOK * DIN);

    transpose_split3_kernel<<<dim3(DKQ / 32, DIN / 32, 3), 256>>>(
        Wq, WtQ0, WtQ1, Wk, WtK0, WtK1, Wv, WtV0, WtV1, DIN, DKQ);

    // persistent grids: 148 CTAs = 74 cg2 pairs
    const dim3 gPers(148, 1, 1);
    mma_gemm<3><<<gPers, 256, GEMM_SMEM>>>(mx0, mx1, mWq0, mWq1,
                                           x0, x1, WtQ0, WtQ1, DKQ, DIN,
                                           nullptr, Q0, Q1, nullptr, nullptr);
    mma_gemm<3><<<gPers, 256, GEMM_SMEM>>>(mx0, mx1, mWk0, mWk1,
                                           x0, x1, WtK0, WtK1, DKQ, DIN,
                                           nullptr, K0, K1, nullptr, nullptr);
    // V = x @ Wv  -> store V^T splits directly (EPI 4)
    mma_gemm<4><<<gPers, 256, GEMM_SMEM>>>(mx0, mx1, mWv0, mWv1,
                                           x0, x1, WtV0, WtV1, DV, DIN,
                                           nullptr, Vt0, Vt1, nullptr, nullptr);

    // scores = (Q @ K^T + channel bias) * rsqrt(dkq)   <- ncu capture target
    mma_gemm<1><<<gPers, 256, GEMM_SMEM>>>(mQ0, mQ1, mK0, mK1,
                                           Q0, Q1, K0, K1, NTOK, DKQ,
                                           S, nullptr, nullptr, nullptr, nullptr);

    // softmax -> P splits
    softmax_split_kernel<<<NTOK, 256>>>(S, P0, P1);

    // ctx = P @ V + b_channel + b_t[0] + pe_row(0)
    mma_gemm<2><<<gPers, 256, GEMM_SMEM>>>(mP0, mP1, mV0, mV1,
                                           P0, P1, Vt0, Vt1, DV, NTOK,
                                           out, nullptr, nullptr, bch, bt);
}